// round 9
// baseline (speedup 1.0000x reference)
#include <cuda_runtime.h>
#include <math.h>

#define NBATCH 1024
#define NUMT   100
#define AOBS   8.0f
#define BOBS   4.2f

// ---------------- device scratch ----------------
__device__ float g_X1[NBATCH * 256];
__device__ float g_H1[NBATCH * 1024];
__device__ float g_H2[NBATCH * 1024];
__device__ float g_X2[NBATCH * 64];
__device__ float g_nn[NBATCH * 8];

__device__ float g_inv1x[11 * 14];
__device__ float g_inv1y[11 * 15];
__device__ float g_inv2x[11 * 14];
__device__ float g_inv2y[11 * 15];
__device__ float g_Mx[121];
__device__ float g_My[121];
__device__ float g_GAvd[4 * 11];
__device__ float g_GApd[4 * 11];

// ---------------- setup: Grams + KKT inverses (fp64 Gauss-Jordan) ----------------
// blocks: 0->inv1x(14) 1->inv1y(15) 2->inv2x(14) 3->inv2y(15)
__global__ __launch_bounds__(128) void setup_kernel(
    const float* __restrict__ P, const float* __restrict__ Pd, const float* __restrict__ Pdd)
{
    __shared__ double SP[121], SD[121], SDD[121], SAV[121], SAP[121];
    __shared__ double M[15 * 30];
    __shared__ double fac[15];
    __shared__ double spinv;
    __shared__ int spiv;

    const int tid = threadIdx.x;
    const int m = blockIdx.x;
    const double KD = 2.0 * sqrt(20.0);

    for (int e = tid; e < 121; e += 128) {
        int i = e / 11, j = e % 11;
        double sp = 0, sd = 0, sdd = 0, sav = 0, sap = 0;
        for (int t = 0; t < NUMT; t++) {
            double pi = P[t * 11 + i],  pj = P[t * 11 + j];
            double di = Pd[t * 11 + i], dj = Pd[t * 11 + j];
            double ai = Pdd[t * 11 + i], aj = Pdd[t * 11 + j];
            sp += pi * pj; sd += di * dj; sdd += ai * aj;
            double avi = ai - 20.0 * di, avj = aj - 20.0 * dj;
            sav += avi * avj;
            double api = ai - 20.0 * pi - KD * di, apj = aj - 20.0 * pj - KD * dj;
            sap += api * apj;
        }
        SP[e] = sp; SD[e] = sd; SDD[e] = sdd; SAV[e] = sav; SAP[e] = sap;
    }
    __syncthreads();

    const int n = (m == 0 || m == 2) ? 14 : 15;
    const int n2 = 2 * n;

    for (int e = tid; e < n * n2; e += 128) {
        int i = e / n2, j = e % n2;
        double val;
        if (j >= n) {
            val = ((j - n) == i) ? 1.0 : 0.0;
        } else if (i < 11 && j < 11) {
            int e2 = i * 11 + j;
            if (m == 0)      val = SDD[e2] + SAV[e2];
            else if (m == 1) val = SDD[e2] + SAP[e2];
            else {
                val = 1000.0 * SP[e2] + 100.0 * (SDD[e2] + SD[e2]);
                if (i == j) val += 1.0;
                if (m == 3) val += 200.0 * SP[e2];
            }
        } else if (i >= 11 && j < 11) {
            int r = i - 11;
            val = (r == 0) ? (double)P[j] : (r == 1) ? (double)Pd[j] :
                  (r == 2) ? (double)Pdd[j] : (double)Pd[99 * 11 + j];
        } else if (j >= 11 && i < 11) {
            int r = j - 11;
            val = (r == 0) ? (double)P[i] : (r == 1) ? (double)Pd[i] :
                  (r == 2) ? (double)Pdd[i] : (double)Pd[99 * 11 + i];
        } else val = 0.0;
        M[i * n2 + j] = val;
    }
    __syncthreads();

    for (int k = 0; k < n; k++) {
        if (tid == 0) {
            int piv = k; double best = fabs(M[k * n2 + k]);
            for (int r = k + 1; r < n; r++) {
                double vv = fabs(M[r * n2 + k]);
                if (vv > best) { best = vv; piv = r; }
            }
            spiv = piv;
        }
        __syncthreads();
        int piv = spiv;
        if (piv != k)
            for (int j = tid; j < n2; j += 128) {
                double t = M[k * n2 + j]; M[k * n2 + j] = M[piv * n2 + j]; M[piv * n2 + j] = t;
            }
        __syncthreads();
        if (tid == 0) spinv = 1.0 / M[k * n2 + k];
        __syncthreads();
        for (int j = tid; j < n2; j += 128) M[k * n2 + j] *= spinv;
        __syncthreads();
        for (int i = tid; i < n; i += 128) fac[i] = M[i * n2 + k];
        __syncthreads();
        for (int e = tid; e < n * n2; e += 128) {
            int i = e / n2, j = e % n2;
            if (i != k) M[i * n2 + j] -= fac[i] * M[k * n2 + j];
        }
        __syncthreads();
    }

    float* dst = (m == 0) ? g_inv1x : (m == 1) ? g_inv1y : (m == 2) ? g_inv2x : g_inv2y;
    for (int e = tid; e < 11 * n; e += 128) {
        int i = e / n, j = e % n;
        dst[e] = (float)M[i * n2 + n + j];
    }
    if (m == 0) {
        for (int e = tid; e < 121; e += 128) {
            float mx = (float)(1000.0 * SP[e] + 100.0 * (SD[e] + SDD[e]));
            g_Mx[e] = mx;
            g_My[e] = mx + (float)(200.0 * SP[e]);
        }
        for (int e = tid; e < 44; e += 128) {
            int g = e / 11, j = e % 11;
            double sv = 0, sp2 = 0;
            for (int t = 25 * g; t < 25 * g + 25; t++) {
                sv  += (double)Pdd[t * 11 + j] - 20.0 * Pd[t * 11 + j];
                sp2 += (double)Pdd[t * 11 + j] - 20.0 * P[t * 11 + j] - KD * Pd[t * 11 + j];
            }
            g_GAvd[e] = (float)sv;
            g_GApd[e] = (float)sp2;
        }
    }
}

// ---------------- build encoder input ----------------
__global__ void build_x1(const float* __restrict__ inp, const float* __restrict__ traj,
                         const float* __restrict__ mean, const float* __restrict__ stdv)
{
    int idx = blockIdx.x * blockDim.x + threadIdx.x;
    if (idx >= NBATCH * 256) return;
    int b = idx >> 8, c = idx & 255;
    float val;
    if (c < 55)       val = (inp[b * 55 + c] - mean[c]) / stdv[c];
    else if (c < 255) val = traj[b * 200 + c - 55];
    else              val = 0.f;
    g_X1[idx] = val;
}

// ---------------- fp32 GEMM: C = [relu](A @ W + bias), A zero-padded to lda ----------------
#define BM 64
#define BN 128
#define BKQ 16
__global__ __launch_bounds__(256) void gemm_bias_relu(
    const float* __restrict__ A, int lda,
    const float* __restrict__ W, const float* __restrict__ bias,
    float* __restrict__ C, int N, int K, int do_relu)
{
    __shared__ float As[BKQ][BM];
    __shared__ float Bs[BKQ][BN];
    const int tid = threadIdx.x;
    const int bm0 = blockIdx.y * BM;
    const int bn0 = blockIdx.x * BN;
    const int tx = tid & 15, ty = tid >> 4;
    const int arow = tid >> 2, acol4 = (tid & 3) * 4;

    float acc[4][8];
#pragma unroll
    for (int i = 0; i < 4; i++)
#pragma unroll
        for (int j = 0; j < 8; j++) acc[i][j] = 0.f;

    const int kt_end = (K + BKQ - 1) / BKQ;
    for (int kt = 0; kt < kt_end; kt++) {
        const int k0 = kt * BKQ;
        float4 a4 = *reinterpret_cast<const float4*>(&A[(bm0 + arow) * lda + k0 + acol4]);
        As[acol4 + 0][arow] = a4.x;
        As[acol4 + 1][arow] = a4.y;
        As[acol4 + 2][arow] = a4.z;
        As[acol4 + 3][arow] = a4.w;
#pragma unroll
        for (int i = 0; i < 2; i++) {
            int idx = tid + 256 * i;
            int brow = idx >> 5, bcol = (idx & 31) * 4;
            int gk = k0 + brow;
            float4 b4 = make_float4(0.f, 0.f, 0.f, 0.f);
            if (gk < K) b4 = *reinterpret_cast<const float4*>(&W[gk * N + bn0 + bcol]);
            *reinterpret_cast<float4*>(&Bs[brow][bcol]) = b4;
        }
        __syncthreads();
#pragma unroll
        for (int k = 0; k < BKQ; k++) {
            float4 av = *reinterpret_cast<float4*>(&As[k][ty * 4]);
            float4 b0 = *reinterpret_cast<float4*>(&Bs[k][tx * 8]);
            float4 b1 = *reinterpret_cast<float4*>(&Bs[k][tx * 8 + 4]);
            float am[4] = {av.x, av.y, av.z, av.w};
            float bv[8] = {b0.x, b0.y, b0.z, b0.w, b1.x, b1.y, b1.z, b1.w};
#pragma unroll
            for (int i = 0; i < 4; i++)
#pragma unroll
                for (int j = 0; j < 8; j++) acc[i][j] = fmaf(am[i], bv[j], acc[i][j]);
        }
        __syncthreads();
    }

    float bb[8];
#pragma unroll
    for (int j = 0; j < 8; j++) bb[j] = bias[bn0 + tx * 8 + j];
#pragma unroll
    for (int i = 0; i < 4; i++) {
        float vout[8];
#pragma unroll
        for (int j = 0; j < 8; j++) {
            float x = acc[i][j] + bb[j];
            vout[j] = do_relu ? fmaxf(x, 0.f) : x;
        }
        float* cp = &C[(bm0 + ty * 4 + i) * N + bn0 + tx * 8];
        *reinterpret_cast<float4*>(cp) = make_float4(vout[0], vout[1], vout[2], vout[3]);
        *reinterpret_cast<float4*>(cp + 4) = make_float4(vout[4], vout[5], vout[6], vout[7]);
    }
}

// ---------------- mu/logvar/z + decoder input ----------------
__global__ __launch_bounds__(128) void zdec_kernel(
    const float* __restrict__ wmu, const float* __restrict__ bmu,
    const float* __restrict__ wlv, const float* __restrict__ blv,
    const float* __restrict__ eps)
{
    __shared__ float sred[4];
    const int b = blockIdx.x, tid = threadIdx.x;
    const int warp = tid >> 5, lane = tid & 31;
    const float* h = g_H2 + b * 1024;
    const float* w = (warp < 2) ? wmu : wlv;
    const int c = warp & 1;
    float s = 0.f;
    for (int k = lane; k < 1024; k += 32) s = fmaf(h[k], w[k * 2 + c], s);
#pragma unroll
    for (int off = 16; off; off >>= 1) s += __shfl_down_sync(0xffffffffu, s, off);
    if (lane == 0) sred[warp] = s;
    __syncthreads();
    if (tid < 2) {
        float mu = sred[tid] + bmu[tid];
        float lv = sred[2 + tid] + blv[tid];
        g_X2[b * 64 + tid] = mu + expf(0.5f * lv) * eps[b * 2 + tid];
    }
    for (int i = tid; i < 62; i += 128) {
        int d = 2 + i;
        g_X2[b * 64 + d] = (d < 57) ? g_X1[b * 256 + d - 2] : 0.f;
    }
}

// ---------------- final 8-wide projection ----------------
__global__ __launch_bounds__(256) void nn8_kernel(const float* __restrict__ w3,
                                                  const float* __restrict__ b3)
{
    const int b = blockIdx.x, tid = threadIdx.x;
    const int warp = tid >> 5, lane = tid & 31;
    const float* h = g_H2 + b * 1024;
    float s = 0.f;
    for (int k = lane; k < 1024; k += 32) s = fmaf(h[k], w3[k * 8 + warp], s);
#pragma unroll
    for (int off = 16; off; off >>= 1) s += __shfl_down_sync(0xffffffffu, s, off);
    if (lane == 0) g_nn[b * 8 + warp] = s + b3[warp];
}

// ---------------- solver: 20 ADMM iterations, 1 block / batch row ----------------
__global__ __launch_bounds__(128) void solver_kernel(
    const float* __restrict__ P, const float* __restrict__ Pd, const float* __restrict__ Pdd,
    const float* __restrict__ ise, const float* __restrict__ yub, const float* __restrict__ ylb,
    const float* __restrict__ inp, float* __restrict__ out)
{
    __shared__ float sP[1100], sPd[1100], sPdd[1100];
    __shared__ float v[700];
    __shared__ float red[77];
    __shared__ float cx[11], cy[11], lxs[11], lys[11], cxb[11], cyb[11];
    __shared__ float ex[11], ey[11], linx[11], liny[11];
    __shared__ float sMx[121], sMy[121];
    __shared__ float sI2x[154], sI2y[165];
    __shared__ float sobs[40], snn[8], scal[4];

    const int b = blockIdx.x, tid = threadIdx.x;

    for (int e = tid; e < 1100; e += 128) { sP[e] = P[e]; sPd[e] = Pd[e]; sPdd[e] = Pdd[e]; }
    for (int e = tid; e < 121; e += 128) { sMx[e] = g_Mx[e]; sMy[e] = g_My[e]; }
    for (int e = tid; e < 154; e += 128) sI2x[e] = g_inv2x[e];
    for (int e = tid; e < 165; e += 128) sI2y[e] = g_inv2y[e];
    if (tid < 40) {
        int o = tid >> 2, c = tid & 3;
        sobs[tid] = inp[b * 55 + 5 + 5 * o + c];   // x, y, vx, vy
    }
    if (tid < 8) snn[tid] = g_nn[b * 8 + tid];
    if (tid == 0) { scal[0] = yub[b]; scal[1] = ylb[b]; scal[2] = ise[b * 4 + 2]; scal[3] = ise[b * 4 + 3]; }
    __syncthreads();

    // lincost from nn_out (piecewise-constant v_des/y_des folded into segment Grams)
    if (tid < 11) {
        float sx_ = 0.f, sy_ = 0.f;
#pragma unroll
        for (int g = 0; g < 4; g++) {
            sx_ = fmaf(snn[g],     g_GAvd[g * 11 + tid], sx_);
            sy_ = fmaf(snn[4 + g], g_GApd[g * 11 + tid], sy_);
        }
        linx[tid] = 20.f * sx_;
        liny[tid] = 20.f * sy_;
    }
    __syncthreads();
    if (tid < 11) {
        int i = tid;
        float cxv = g_inv1x[i * 14 + 12] * scal[2];
        float cyv = g_inv1y[i * 15 + 12] * scal[3];
#pragma unroll
        for (int j = 0; j < 11; j++) {
            cxv = fmaf(-g_inv1x[i * 14 + j], linx[j], cxv);
            cyv = fmaf(-g_inv1y[i * 15 + j], liny[j], cyv);
        }
        cxb[i] = cxv; cyb[i] = cyv; cx[i] = cxv; cy[i] = cyv;
        lxs[i] = 0.f; lys[i] = 0.f;
        ex[i] = sI2x[i * 14 + 12] * scal[2];
        ey[i] = sI2y[i * 15 + 12] * scal[3];
    }

    for (int it = 0; it < 20; it++) {
        __syncthreads();
        if (tid < 100) {
            const int t = tid;
            float x = 0.f, xd = 0.f, xdd = 0.f, y = 0.f, yd = 0.f, ydd = 0.f;
#pragma unroll
            for (int j = 0; j < 11; j++) {
                float a = cx[j], c = cy[j];
                float p = sP[t * 11 + j], pd = sPd[t * 11 + j], pdd = sPdd[t * 11 + j];
                x = fmaf(a, p, x);  xd = fmaf(a, pd, xd);  xdd = fmaf(a, pdd, xdd);
                y = fmaf(c, p, y);  yd = fmaf(c, pd, yd);  ydd = fmaf(c, pdd, ydd);
            }
            const float tt = (15.0f / 99.0f) * t;
            float Rx = 0.f, Ry = 0.f;
#pragma unroll
            for (int o = 0; o < 10; o++) {
                float wc = x - fmaf(sobs[o * 4 + 2], tt, sobs[o * 4 + 0]);
                float ws = y - fmaf(sobs[o * 4 + 3], tt, sobs[o * 4 + 1]);
                float aw = AOBS * ws, bw = BOBS * wc;
                float q = fmaf(aw, aw, bw * bw);
                float rinv = rsqrtf(fmaxf(q, 1e-30f));
                float ca = bw * rinv, sa = aw * rinv;
                float c1 = fmaf(64.f * ca, ca, 17.64f * sa * sa);   // /100 folded
                float c2 = fmaf(8.f * wc, ca, 4.2f * ws * sa);
                float d = fmaxf(1.f, __fdividef(c2, c1));
                Rx += wc - 8.f * d * ca;
                Ry += ws - 4.2f * d * sa;
            }
            float rv2 = fmaf(xd, xd, yd * yd);
            float dv = fminf(fmaxf(sqrtf(rv2), 0.1f), 30.f);
            float fv = 1.f - dv * rsqrtf(fmaxf(rv2, 1e-30f));
            float ra2 = fmaf(xdd, xdd, ydd * ydd);
            float da = fminf(sqrtf(ra2), 8.f);
            float fa = 1.f - da * rsqrtf(fmaxf(ra2, 1e-30f));
            float ycl = fminf(fmaxf(y, scal[1]), scal[0]);
            v[t]       = Rx;
            v[100 + t] = Ry;
            v[200 + t] = xdd * fa;
            v[300 + t] = ydd * fa;
            v[400 + t] = xd * fv;
            v[500 + t] = yd * fv;
            v[600 + t] = y - ycl;
        }
        __syncthreads();
        if (tid < 77) {
            const int q = tid / 11, j = tid % 11;
            const float* basis = (q == 2 || q == 3) ? sPdd : (q == 4 || q == 5) ? sPd : sP;
            const float* vv = v + q * 100;
            float s = 0.f;
            for (int t = 0; t < 100; t++) s = fmaf(vv[t], basis[t * 11 + j], s);
            red[tid] = s;
        }
        __syncthreads();
        if (tid < 11) {
            const int j = tid;
            float Dx = 100.f * (red[j] + red[22 + j] + red[44 + j]);
            float Dy = 100.f * (red[11 + j] + red[33 + j] + red[55 + j] + red[66 + j]);
            float lxn = lxs[j] - Dx, lyn = lys[j] - Dy;
            lxs[j] = lxn; lys[j] = lyn;
            float mx = 0.f, my = 0.f;
#pragma unroll
            for (int i = 0; i < 11; i++) {
                mx = fmaf(cx[i], sMx[i * 11 + j], mx);
                my = fmaf(cy[i], sMy[i * 11 + j], my);
            }
            linx[j] = -lxn + Dx - cxb[j] - mx;
            liny[j] = -lyn + Dy - cyb[j] - my;
        }
        __syncthreads();
        if (tid < 22) {
            const int i = tid % 11;
            if (tid < 11) {
                float s = ex[i];
#pragma unroll
                for (int j = 0; j < 11; j++) s = fmaf(-sI2x[i * 14 + j], linx[j], s);
                cx[i] = s;
            } else {
                float s = ey[i];
#pragma unroll
                for (int j = 0; j < 11; j++) s = fmaf(-sI2y[i * 15 + j], liny[j], s);
                cy[i] = s;
            }
        }
    }
    __syncthreads();
    if (tid < 22) out[b * 22 + tid] = (tid < 11) ? cx[tid] : cy[tid - 11];
}

// ---------------- launch ----------------
extern "C" void kernel_launch(void* const* d_in, const int* in_sizes, int n_in,
                              void* d_out, int out_size)
{
    const float* inp  = (const float*)d_in[0];
    const float* ise  = (const float*)d_in[1];
    const float* traj = (const float*)d_in[2];
    const float* yub  = (const float*)d_in[3];
    const float* ylb  = (const float*)d_in[4];
    const float* eps  = (const float*)d_in[5];
    const float* ew1  = (const float*)d_in[6];
    const float* eb1  = (const float*)d_in[7];
    const float* ew2  = (const float*)d_in[8];
    const float* eb2  = (const float*)d_in[9];
    const float* wmu  = (const float*)d_in[10];
    const float* bmu  = (const float*)d_in[11];
    const float* wlv  = (const float*)d_in[12];
    const float* blv  = (const float*)d_in[13];
    const float* dw1  = (const float*)d_in[14];
    const float* db1  = (const float*)d_in[15];
    const float* dw2  = (const float*)d_in[16];
    const float* db2  = (const float*)d_in[17];
    const float* dw3  = (const float*)d_in[18];
    const float* db3  = (const float*)d_in[19];
    const float* P    = (const float*)d_in[20];
    const float* Pd   = (const float*)d_in[21];
    const float* Pdd  = (const float*)d_in[22];
    const float* imean = (const float*)d_in[23];
    const float* istd  = (const float*)d_in[24];
    float* out = (float*)d_out;

    float *pX1, *pH1, *pH2, *pX2;
    cudaGetSymbolAddress((void**)&pX1, g_X1);
    cudaGetSymbolAddress((void**)&pH1, g_H1);
    cudaGetSymbolAddress((void**)&pH2, g_H2);
    cudaGetSymbolAddress((void**)&pX2, g_X2);

    setup_kernel<<<4, 128>>>(P, Pd, Pdd);
    build_x1<<<(NBATCH * 256) / 256, 256>>>(inp, traj, imean, istd);

    dim3 gg(1024 / BN, 1024 / BM);
    gemm_bias_relu<<<gg, 256>>>(pX1, 256, ew1, eb1, pH1, 1024, 255, 1);
    gemm_bias_relu<<<gg, 256>>>(pH1, 1024, ew2, eb2, pH2, 1024, 1024, 1);
    zdec_kernel<<<NBATCH, 128>>>(wmu, bmu, wlv, blv, eps);
    gemm_bias_relu<<<gg, 256>>>(pX2, 64, dw1, db1, pH1, 1024, 57, 1);
    gemm_bias_relu<<<gg, 256>>>(pH1, 1024, dw2, db2, pH2, 1024, 1024, 1);
    nn8_kernel<<<NBATCH, 256>>>(dw3, db3);
    solver_kernel<<<NBATCH, 128>>>(P, Pd, Pdd, ise, yub, ylb, inp, out);
}

// round 10
// speedup vs baseline: 1.1986x; 1.1986x over previous
#include <cuda_runtime.h>
#include <math.h>

#define NBATCH 1024
#define NUMT   100
#define AOBS   8.0f
#define BOBS   4.2f

// ---------------- device scratch ----------------
__device__ float g_X1[NBATCH * 256];
__device__ float g_H1[NBATCH * 1024];
__device__ float g_H2[NBATCH * 1024];
__device__ float g_X2[NBATCH * 64];
__device__ float g_nn[NBATCH * 8];

__device__ float g_inv1x[11 * 14];
__device__ float g_inv1y[11 * 15];
__device__ float g_inv2x[11 * 14];
__device__ float g_inv2y[11 * 15];
__device__ float g_Mx[121];
__device__ float g_My[121];
__device__ float g_GAvd[4 * 11];
__device__ float g_GApd[4 * 11];

// ---------------- setup: Grams + KKT inverses (fp64 Gauss-Jordan) ----------------
// blocks: 0->inv1x(14) 1->inv1y(15) 2->inv2x(14) 3->inv2y(15)
__global__ __launch_bounds__(128) void setup_kernel(
    const float* __restrict__ P, const float* __restrict__ Pd, const float* __restrict__ Pdd)
{
    __shared__ double SP[121], SD[121], SDD[121], SAV[121], SAP[121];
    __shared__ double M[15 * 30];
    __shared__ double fac[15];
    __shared__ double spinv;
    __shared__ int spiv;

    const int tid = threadIdx.x;
    const int m = blockIdx.x;
    const double KD = 2.0 * sqrt(20.0);

    for (int e = tid; e < 121; e += 128) {
        int i = e / 11, j = e % 11;
        double sp = 0, sd = 0, sdd = 0, sav = 0, sap = 0;
        for (int t = 0; t < NUMT; t++) {
            double pi = P[t * 11 + i],  pj = P[t * 11 + j];
            double di = Pd[t * 11 + i], dj = Pd[t * 11 + j];
            double ai = Pdd[t * 11 + i], aj = Pdd[t * 11 + j];
            sp += pi * pj; sd += di * dj; sdd += ai * aj;
            double avi = ai - 20.0 * di, avj = aj - 20.0 * dj;
            sav += avi * avj;
            double api = ai - 20.0 * pi - KD * di, apj = aj - 20.0 * pj - KD * dj;
            sap += api * apj;
        }
        SP[e] = sp; SD[e] = sd; SDD[e] = sdd; SAV[e] = sav; SAP[e] = sap;
    }
    __syncthreads();

    const int n = (m == 0 || m == 2) ? 14 : 15;
    const int n2 = 2 * n;

    for (int e = tid; e < n * n2; e += 128) {
        int i = e / n2, j = e % n2;
        double val;
        if (j >= n) {
            val = ((j - n) == i) ? 1.0 : 0.0;
        } else if (i < 11 && j < 11) {
            int e2 = i * 11 + j;
            if (m == 0)      val = SDD[e2] + SAV[e2];
            else if (m == 1) val = SDD[e2] + SAP[e2];
            else {
                val = 1000.0 * SP[e2] + 100.0 * (SDD[e2] + SD[e2]);
                if (i == j) val += 1.0;
                if (m == 3) val += 200.0 * SP[e2];
            }
        } else if (i >= 11 && j < 11) {
            int r = i - 11;
            val = (r == 0) ? (double)P[j] : (r == 1) ? (double)Pd[j] :
                  (r == 2) ? (double)Pdd[j] : (double)Pd[99 * 11 + j];
        } else if (j >= 11 && i < 11) {
            int r = j - 11;
            val = (r == 0) ? (double)P[i] : (r == 1) ? (double)Pd[i] :
                  (r == 2) ? (double)Pdd[i] : (double)Pd[99 * 11 + i];
        } else val = 0.0;
        M[i * n2 + j] = val;
    }
    __syncthreads();

    for (int k = 0; k < n; k++) {
        if (tid == 0) {
            int piv = k; double best = fabs(M[k * n2 + k]);
            for (int r = k + 1; r < n; r++) {
                double vv = fabs(M[r * n2 + k]);
                if (vv > best) { best = vv; piv = r; }
            }
            spiv = piv;
        }
        __syncthreads();
        int piv = spiv;
        if (piv != k)
            for (int j = tid; j < n2; j += 128) {
                double t = M[k * n2 + j]; M[k * n2 + j] = M[piv * n2 + j]; M[piv * n2 + j] = t;
            }
        __syncthreads();
        if (tid == 0) spinv = 1.0 / M[k * n2 + k];
        __syncthreads();
        for (int j = tid; j < n2; j += 128) M[k * n2 + j] *= spinv;
        __syncthreads();
        for (int i = tid; i < n; i += 128) fac[i] = M[i * n2 + k];
        __syncthreads();
        for (int e = tid; e < n * n2; e += 128) {
            int i = e / n2, j = e % n2;
            if (i != k) M[i * n2 + j] -= fac[i] * M[k * n2 + j];
        }
        __syncthreads();
    }

    float* dst = (m == 0) ? g_inv1x : (m == 1) ? g_inv1y : (m == 2) ? g_inv2x : g_inv2y;
    for (int e = tid; e < 11 * n; e += 128) {
        int i = e / n, j = e % n;
        dst[e] = (float)M[i * n2 + n + j];
    }
    if (m == 0) {
        for (int e = tid; e < 121; e += 128) {
            float mx = (float)(1000.0 * SP[e] + 100.0 * (SD[e] + SDD[e]));
            g_Mx[e] = mx;
            g_My[e] = mx + (float)(200.0 * SP[e]);
        }
        for (int e = tid; e < 44; e += 128) {
            int g = e / 11, j = e % 11;
            double sv = 0, sp2 = 0;
            for (int t = 25 * g; t < 25 * g + 25; t++) {
                sv  += (double)Pdd[t * 11 + j] - 20.0 * Pd[t * 11 + j];
                sp2 += (double)Pdd[t * 11 + j] - 20.0 * P[t * 11 + j] - KD * Pd[t * 11 + j];
            }
            g_GAvd[e] = (float)sv;
            g_GApd[e] = (float)sp2;
        }
    }
}

// ---------------- build encoder input ----------------
__global__ void build_x1(const float* __restrict__ inp, const float* __restrict__ traj,
                         const float* __restrict__ mean, const float* __restrict__ stdv)
{
    int idx = blockIdx.x * blockDim.x + threadIdx.x;
    if (idx >= NBATCH * 256) return;
    int b = idx >> 8, c = idx & 255;
    float val;
    if (c < 55)       val = (inp[b * 55 + c] - mean[c]) / stdv[c];
    else if (c < 255) val = traj[b * 200 + c - 55];
    else              val = 0.f;
    g_X1[idx] = val;
}

// ---------------- fp32 GEMM: C = [relu](A @ W + bias), A zero-padded to lda ----------------
// 64x64 tile, 256 threads, 4x4 per thread, BK=16 -> 256 CTAs on a 1024x1024 output
#define BM 64
#define BN 64
#define BKQ 16
__global__ __launch_bounds__(256, 2) void gemm_bias_relu(
    const float* __restrict__ A, int lda,
    const float* __restrict__ W, const float* __restrict__ bias,
    float* __restrict__ C, int N, int K, int do_relu)
{
    __shared__ float As[BKQ][BM];
    __shared__ float Bs[BKQ][BN];
    const int tid = threadIdx.x;
    const int bm0 = blockIdx.y * BM;
    const int bn0 = blockIdx.x * BN;
    const int tx = tid & 15, ty = tid >> 4;        // 16 x 16 thread grid, 4x4 each
    const int arow = tid >> 2, acol4 = (tid & 3) * 4;
    const int brow = tid >> 4, bcol = (tid & 15) * 4;

    float acc[4][4];
#pragma unroll
    for (int i = 0; i < 4; i++)
#pragma unroll
        for (int j = 0; j < 4; j++) acc[i][j] = 0.f;

    const int kt_end = (K + BKQ - 1) / BKQ;
    for (int kt = 0; kt < kt_end; kt++) {
        const int k0 = kt * BKQ;
        // A tile 64x16 (transposed into smem); padded A rows make this always in-bounds
        float4 a4 = *reinterpret_cast<const float4*>(&A[(bm0 + arow) * lda + k0 + acol4]);
        As[acol4 + 0][arow] = a4.x;
        As[acol4 + 1][arow] = a4.y;
        As[acol4 + 2][arow] = a4.z;
        As[acol4 + 3][arow] = a4.w;
        // W tile 16x64
        {
            int gk = k0 + brow;
            float4 b4 = make_float4(0.f, 0.f, 0.f, 0.f);
            if (gk < K) b4 = *reinterpret_cast<const float4*>(&W[gk * N + bn0 + bcol]);
            *reinterpret_cast<float4*>(&Bs[brow][bcol]) = b4;
        }
        __syncthreads();
#pragma unroll
        for (int k = 0; k < BKQ; k++) {
            float4 av = *reinterpret_cast<float4*>(&As[k][ty * 4]);
            float4 bv = *reinterpret_cast<float4*>(&Bs[k][tx * 4]);
            float am[4] = {av.x, av.y, av.z, av.w};
            float bb[4] = {bv.x, bv.y, bv.z, bv.w};
#pragma unroll
            for (int i = 0; i < 4; i++)
#pragma unroll
                for (int j = 0; j < 4; j++) acc[i][j] = fmaf(am[i], bb[j], acc[i][j]);
        }
        __syncthreads();
    }

    float4 bias4 = *reinterpret_cast<const float4*>(&bias[bn0 + tx * 4]);
    float bb[4] = {bias4.x, bias4.y, bias4.z, bias4.w};
#pragma unroll
    for (int i = 0; i < 4; i++) {
        float vout[4];
#pragma unroll
        for (int j = 0; j < 4; j++) {
            float x = acc[i][j] + bb[j];
            vout[j] = do_relu ? fmaxf(x, 0.f) : x;
        }
        float* cp = &C[(bm0 + ty * 4 + i) * N + bn0 + tx * 4];
        *reinterpret_cast<float4*>(cp) = make_float4(vout[0], vout[1], vout[2], vout[3]);
    }
}

// ---------------- mu/logvar/z + decoder input ----------------
__global__ __launch_bounds__(128) void zdec_kernel(
    const float* __restrict__ wmu, const float* __restrict__ bmu,
    const float* __restrict__ wlv, const float* __restrict__ blv,
    const float* __restrict__ eps)
{
    __shared__ float sred[4];
    const int b = blockIdx.x, tid = threadIdx.x;
    const int warp = tid >> 5, lane = tid & 31;
    const float* h = g_H2 + b * 1024;
    const float* w = (warp < 2) ? wmu : wlv;
    const int c = warp & 1;
    float s = 0.f;
    for (int k = lane; k < 1024; k += 32) s = fmaf(h[k], w[k * 2 + c], s);
#pragma unroll
    for (int off = 16; off; off >>= 1) s += __shfl_down_sync(0xffffffffu, s, off);
    if (lane == 0) sred[warp] = s;
    __syncthreads();
    if (tid < 2) {
        float mu = sred[tid] + bmu[tid];
        float lv = sred[2 + tid] + blv[tid];
        g_X2[b * 64 + tid] = mu + expf(0.5f * lv) * eps[b * 2 + tid];
    }
    for (int i = tid; i < 62; i += 128) {
        int d = 2 + i;
        g_X2[b * 64 + d] = (d < 57) ? g_X1[b * 256 + d - 2] : 0.f;
    }
}

// ---------------- final 8-wide projection ----------------
__global__ __launch_bounds__(256) void nn8_kernel(const float* __restrict__ w3,
                                                  const float* __restrict__ b3)
{
    const int b = blockIdx.x, tid = threadIdx.x;
    const int warp = tid >> 5, lane = tid & 31;
    const float* h = g_H2 + b * 1024;
    float s = 0.f;
    for (int k = lane; k < 1024; k += 32) s = fmaf(h[k], w3[k * 8 + warp], s);
#pragma unroll
    for (int off = 16; off; off >>= 1) s += __shfl_down_sync(0xffffffffu, s, off);
    if (lane == 0) g_nn[b * 8 + warp] = s + b3[warp];
}

// ---------------- solver: 20 ADMM iterations, 1 block / batch row ----------------
__global__ __launch_bounds__(128) void solver_kernel(
    const float* __restrict__ P, const float* __restrict__ Pd, const float* __restrict__ Pdd,
    const float* __restrict__ ise, const float* __restrict__ yub, const float* __restrict__ ylb,
    const float* __restrict__ inp, float* __restrict__ out)
{
    __shared__ float sP[1100], sPd[1100], sPdd[1100];
    __shared__ float v[700];
    __shared__ float red[77];
    __shared__ float cx[11], cy[11], lxs[11], lys[11], cxb[11], cyb[11];
    __shared__ float ex[11], ey[11], linx[11], liny[11];
    __shared__ float sMx[121], sMy[121];
    __shared__ float sI2x[154], sI2y[165];
    __shared__ float sobs[40], snn[8], scal[4];

    const int b = blockIdx.x, tid = threadIdx.x;

    for (int e = tid; e < 1100; e += 128) { sP[e] = P[e]; sPd[e] = Pd[e]; sPdd[e] = Pdd[e]; }
    for (int e = tid; e < 121; e += 128) { sMx[e] = g_Mx[e]; sMy[e] = g_My[e]; }
    for (int e = tid; e < 154; e += 128) sI2x[e] = g_inv2x[e];
    for (int e = tid; e < 165; e += 128) sI2y[e] = g_inv2y[e];
    if (tid < 40) {
        int o = tid >> 2, c = tid & 3;
        sobs[tid] = inp[b * 55 + 5 + 5 * o + c];   // x, y, vx, vy
    }
    if (tid < 8) snn[tid] = g_nn[b * 8 + tid];
    if (tid == 0) { scal[0] = yub[b]; scal[1] = ylb[b]; scal[2] = ise[b * 4 + 2]; scal[3] = ise[b * 4 + 3]; }
    __syncthreads();

    if (tid < 11) {
        float sx_ = 0.f, sy_ = 0.f;
#pragma unroll
        for (int g = 0; g < 4; g++) {
            sx_ = fmaf(snn[g],     g_GAvd[g * 11 + tid], sx_);
            sy_ = fmaf(snn[4 + g], g_GApd[g * 11 + tid], sy_);
        }
        linx[tid] = 20.f * sx_;
        liny[tid] = 20.f * sy_;
    }
    __syncthreads();
    if (tid < 11) {
        int i = tid;
        float cxv = g_inv1x[i * 14 + 12] * scal[2];
        float cyv = g_inv1y[i * 15 + 12] * scal[3];
#pragma unroll
        for (int j = 0; j < 11; j++) {
            cxv = fmaf(-g_inv1x[i * 14 + j], linx[j], cxv);
            cyv = fmaf(-g_inv1y[i * 15 + j], liny[j], cyv);
        }
        cxb[i] = cxv; cyb[i] = cyv; cx[i] = cxv; cy[i] = cyv;
        lxs[i] = 0.f; lys[i] = 0.f;
        ex[i] = sI2x[i * 14 + 12] * scal[2];
        ey[i] = sI2y[i * 15 + 12] * scal[3];
    }

    for (int it = 0; it < 20; it++) {
        __syncthreads();
        if (tid < 100) {
            const int t = tid;
            float x = 0.f, xd = 0.f, xdd = 0.f, y = 0.f, yd = 0.f, ydd = 0.f;
#pragma unroll
            for (int j = 0; j < 11; j++) {
                float a = cx[j], c = cy[j];
                float p = sP[t * 11 + j], pd = sPd[t * 11 + j], pdd = sPdd[t * 11 + j];
                x = fmaf(a, p, x);  xd = fmaf(a, pd, xd);  xdd = fmaf(a, pdd, xdd);
                y = fmaf(c, p, y);  yd = fmaf(c, pd, yd);  ydd = fmaf(c, pdd, ydd);
            }
            const float tt = (15.0f / 99.0f) * t;
            float Rx = 0.f, Ry = 0.f;
#pragma unroll
            for (int o = 0; o < 10; o++) {
                float wc = x - fmaf(sobs[o * 4 + 2], tt, sobs[o * 4 + 0]);
                float ws = y - fmaf(sobs[o * 4 + 3], tt, sobs[o * 4 + 1]);
                float aw = AOBS * ws, bw = BOBS * wc;
                float q = fmaf(aw, aw, bw * bw);
                float rinv = rsqrtf(fmaxf(q, 1e-30f));
                float ca = bw * rinv, sa = aw * rinv;
                float c1 = fmaf(64.f * ca, ca, 17.64f * sa * sa);
                float c2 = fmaf(8.f * wc, ca, 4.2f * ws * sa);
                float d = fmaxf(1.f, __fdividef(c2, c1));
                Rx += wc - 8.f * d * ca;
                Ry += ws - 4.2f * d * sa;
            }
            float rv2 = fmaf(xd, xd, yd * yd);
            float dv = fminf(fmaxf(sqrtf(rv2), 0.1f), 30.f);
            float fv = 1.f - dv * rsqrtf(fmaxf(rv2, 1e-30f));
            float ra2 = fmaf(xdd, xdd, ydd * ydd);
            float da = fminf(sqrtf(ra2), 8.f);
            float fa = 1.f - da * rsqrtf(fmaxf(ra2, 1e-30f));
            float ycl = fminf(fmaxf(y, scal[1]), scal[0]);
            v[t]       = Rx;
            v[100 + t] = Ry;
            v[200 + t] = xdd * fa;
            v[300 + t] = ydd * fa;
            v[400 + t] = xd * fv;
            v[500 + t] = yd * fv;
            v[600 + t] = y - ycl;
        }
        __syncthreads();
        if (tid < 77) {
            const int q = tid / 11, j = tid % 11;
            const float* basis = (q == 2 || q == 3) ? sPdd : (q == 4 || q == 5) ? sPd : sP;
            const float* vv = v + q * 100;
            float s = 0.f;
            for (int t = 0; t < 100; t++) s = fmaf(vv[t], basis[t * 11 + j], s);
            red[tid] = s;
        }
        __syncthreads();
        if (tid < 11) {
            const int j = tid;
            float Dx = 100.f * (red[j] + red[22 + j] + red[44 + j]);
            float Dy = 100.f * (red[11 + j] + red[33 + j] + red[55 + j] + red[66 + j]);
            float lxn = lxs[j] - Dx, lyn = lys[j] - Dy;
            lxs[j] = lxn; lys[j] = lyn;
            float mx = 0.f, my = 0.f;
#pragma unroll
            for (int i = 0; i < 11; i++) {
                mx = fmaf(cx[i], sMx[i * 11 + j], mx);
                my = fmaf(cy[i], sMy[i * 11 + j], my);
            }
            linx[j] = -lxn + Dx - cxb[j] - mx;
            liny[j] = -lyn + Dy - cyb[j] - my;
        }
        __syncthreads();
        if (tid < 22) {
            const int i = tid % 11;
            if (tid < 11) {
                float s = ex[i];
#pragma unroll
                for (int j = 0; j < 11; j++) s = fmaf(-sI2x[i * 14 + j], linx[j], s);
                cx[i] = s;
            } else {
                float s = ey[i];
#pragma unroll
                for (int j = 0; j < 11; j++) s = fmaf(-sI2y[i * 15 + j], liny[j], s);
                cy[i] = s;
            }
        }
    }
    __syncthreads();
    if (tid < 22) out[b * 22 + tid] = (tid < 11) ? cx[tid] : cy[tid - 11];
}

// ---------------- launch ----------------
extern "C" void kernel_launch(void* const* d_in, const int* in_sizes, int n_in,
                              void* d_out, int out_size)
{
    const float* inp  = (const float*)d_in[0];
    const float* ise  = (const float*)d_in[1];
    const float* traj = (const float*)d_in[2];
    const float* yub  = (const float*)d_in[3];
    const float* ylb  = (const float*)d_in[4];
    const float* eps  = (const float*)d_in[5];
    const float* ew1  = (const float*)d_in[6];
    const float* eb1  = (const float*)d_in[7];
    const float* ew2  = (const float*)d_in[8];
    const float* eb2  = (const float*)d_in[9];
    const float* wmu  = (const float*)d_in[10];
    const float* bmu  = (const float*)d_in[11];
    const float* wlv  = (const float*)d_in[12];
    const float* blv  = (const float*)d_in[13];
    const float* dw1  = (const float*)d_in[14];
    const float* db1  = (const float*)d_in[15];
    const float* dw2  = (const float*)d_in[16];
    const float* db2  = (const float*)d_in[17];
    const float* dw3  = (const float*)d_in[18];
    const float* db3  = (const float*)d_in[19];
    const float* P    = (const float*)d_in[20];
    const float* Pd   = (const float*)d_in[21];
    const float* Pdd  = (const float*)d_in[22];
    const float* imean = (const float*)d_in[23];
    const float* istd  = (const float*)d_in[24];
    float* out = (float*)d_out;

    float *pX1, *pH1, *pH2, *pX2;
    cudaGetSymbolAddress((void**)&pX1, g_X1);
    cudaGetSymbolAddress((void**)&pH1, g_H1);
    cudaGetSymbolAddress((void**)&pH2, g_H2);
    cudaGetSymbolAddress((void**)&pX2, g_X2);

    setup_kernel<<<4, 128>>>(P, Pd, Pdd);
    build_x1<<<(NBATCH * 256) / 256, 256>>>(inp, traj, imean, istd);

    dim3 gg(1024 / BN, 1024 / BM);
    gemm_bias_relu<<<gg, 256>>>(pX1, 256, ew1, eb1, pH1, 1024, 255, 1);
    gemm_bias_relu<<<gg, 256>>>(pH1, 1024, ew2, eb2, pH2, 1024, 1024, 1);
    zdec_kernel<<<NBATCH, 128>>>(wmu, bmu, wlv, blv, eps);
    gemm_bias_relu<<<gg, 256>>>(pX2, 64, dw1, db1, pH1, 1024, 57, 1);
    gemm_bias_relu<<<gg, 256>>>(pH1, 1024, dw2, db2, pH2, 1024, 1024, 1);
    nn8_kernel<<<NBATCH, 256>>>(dw3, db3);
    solver_kernel<<<NBATCH, 128>>>(P, Pd, Pdd, ise, yub, ylb, inp, out);
}

// round 11
// speedup vs baseline: 1.4530x; 1.2123x over previous
#include <cuda_runtime.h>
#include <cuda_bf16.h>
#include <math.h>
#include <stdint.h>

#define NBATCH 1024
#define NUMT   100
#define AOBS   8.0f
#define BOBS   4.2f

typedef __nv_bfloat16 bf16;

// ---------------- device scratch ----------------
__device__ bf16 g_X1h[NBATCH * 256], g_X1l[NBATCH * 256];
__device__ bf16 g_H1h[NBATCH * 1024], g_H1l[NBATCH * 1024];
__device__ bf16 g_H2h[NBATCH * 1024], g_H2l[NBATCH * 1024];
__device__ bf16 g_X2h[NBATCH * 64], g_X2l[NBATCH * 64];
__device__ float g_nn[NBATCH * 8];

// transposed + split weights: Wt[n][kp]
__device__ bf16 g_T1h[1024 * 256],  g_T1l[1024 * 256];
__device__ bf16 g_T2h[1024 * 1024], g_T2l[1024 * 1024];
__device__ bf16 g_T3h[1024 * 64],   g_T3l[1024 * 64];
__device__ bf16 g_T4h[1024 * 1024], g_T4l[1024 * 1024];

__device__ float g_inv1x[11 * 14];
__device__ float g_inv1y[11 * 15];
__device__ float g_inv2x[11 * 14];
__device__ float g_inv2y[11 * 15];
__device__ float g_Mx[121];
__device__ float g_My[121];
__device__ float g_GAvd[4 * 11];
__device__ float g_GApd[4 * 11];

// ---------------- setup: Grams + KKT inverses (fp64 Gauss-Jordan) ----------------
__global__ __launch_bounds__(128) void setup_kernel(
    const float* __restrict__ P, const float* __restrict__ Pd, const float* __restrict__ Pdd)
{
    __shared__ double SP[121], SD[121], SDD[121], SAV[121], SAP[121];
    __shared__ double M[15 * 30];
    __shared__ double fac[15];
    __shared__ double spinv;
    __shared__ int spiv;

    const int tid = threadIdx.x;
    const int m = blockIdx.x;
    const double KD = 2.0 * sqrt(20.0);

    for (int e = tid; e < 121; e += 128) {
        int i = e / 11, j = e % 11;
        double sp = 0, sd = 0, sdd = 0, sav = 0, sap = 0;
        for (int t = 0; t < NUMT; t++) {
            double pi = P[t * 11 + i],  pj = P[t * 11 + j];
            double di = Pd[t * 11 + i], dj = Pd[t * 11 + j];
            double ai = Pdd[t * 11 + i], aj = Pdd[t * 11 + j];
            sp += pi * pj; sd += di * dj; sdd += ai * aj;
            double avi = ai - 20.0 * di, avj = aj - 20.0 * dj;
            sav += avi * avj;
            double api = ai - 20.0 * pi - KD * di, apj = aj - 20.0 * pj - KD * dj;
            sap += api * apj;
        }
        SP[e] = sp; SD[e] = sd; SDD[e] = sdd; SAV[e] = sav; SAP[e] = sap;
    }
    __syncthreads();

    const int n = (m == 0 || m == 2) ? 14 : 15;
    const int n2 = 2 * n;

    for (int e = tid; e < n * n2; e += 128) {
        int i = e / n2, j = e % n2;
        double val;
        if (j >= n) {
            val = ((j - n) == i) ? 1.0 : 0.0;
        } else if (i < 11 && j < 11) {
            int e2 = i * 11 + j;
            if (m == 0)      val = SDD[e2] + SAV[e2];
            else if (m == 1) val = SDD[e2] + SAP[e2];
            else {
                val = 1000.0 * SP[e2] + 100.0 * (SDD[e2] + SD[e2]);
                if (i == j) val += 1.0;
                if (m == 3) val += 200.0 * SP[e2];
            }
        } else if (i >= 11 && j < 11) {
            int r = i - 11;
            val = (r == 0) ? (double)P[j] : (r == 1) ? (double)Pd[j] :
                  (r == 2) ? (double)Pdd[j] : (double)Pd[99 * 11 + j];
        } else if (j >= 11 && i < 11) {
            int r = j - 11;
            val = (r == 0) ? (double)P[i] : (r == 1) ? (double)Pd[i] :
                  (r == 2) ? (double)Pdd[i] : (double)Pd[99 * 11 + i];
        } else val = 0.0;
        M[i * n2 + j] = val;
    }
    __syncthreads();

    for (int k = 0; k < n; k++) {
        if (tid == 0) {
            int piv = k; double best = fabs(M[k * n2 + k]);
            for (int r = k + 1; r < n; r++) {
                double vv = fabs(M[r * n2 + k]);
                if (vv > best) { best = vv; piv = r; }
            }
            spiv = piv;
        }
        __syncthreads();
        int piv = spiv;
        if (piv != k)
            for (int j = tid; j < n2; j += 128) {
                double t = M[k * n2 + j]; M[k * n2 + j] = M[piv * n2 + j]; M[piv * n2 + j] = t;
            }
        __syncthreads();
        if (tid == 0) spinv = 1.0 / M[k * n2 + k];
        __syncthreads();
        for (int j = tid; j < n2; j += 128) M[k * n2 + j] *= spinv;
        __syncthreads();
        for (int i = tid; i < n; i += 128) fac[i] = M[i * n2 + k];
        __syncthreads();
        for (int e = tid; e < n * n2; e += 128) {
            int i = e / n2, j = e % n2;
            if (i != k) M[i * n2 + j] -= fac[i] * M[k * n2 + j];
        }
        __syncthreads();
    }

    float* dst = (m == 0) ? g_inv1x : (m == 1) ? g_inv1y : (m == 2) ? g_inv2x : g_inv2y;
    for (int e = tid; e < 11 * n; e += 128) {
        int i = e / n, j = e % n;
        dst[e] = (float)M[i * n2 + n + j];
    }
    if (m == 0) {
        for (int e = tid; e < 121; e += 128) {
            float mx = (float)(1000.0 * SP[e] + 100.0 * (SD[e] + SDD[e]));
            g_Mx[e] = mx;
            g_My[e] = mx + (float)(200.0 * SP[e]);
        }
        for (int e = tid; e < 44; e += 128) {
            int g = e / 11, j = e % 11;
            double sv = 0, sp2 = 0;
            for (int t = 25 * g; t < 25 * g + 25; t++) {
                sv  += (double)Pdd[t * 11 + j] - 20.0 * Pd[t * 11 + j];
                sp2 += (double)Pdd[t * 11 + j] - 20.0 * P[t * 11 + j] - KD * Pd[t * 11 + j];
            }
            g_GAvd[e] = (float)sv;
            g_GApd[e] = (float)sp2;
        }
    }
}

// ---------------- split helper ----------------
__device__ __forceinline__ void split_bf16(float v, bf16& h, bf16& l) {
    h = __float2bfloat16(v);
    l = __float2bfloat16(v - __bfloat162float(h));
}

// ---------------- weight transpose + split: W[K][N] -> Wt[n][Kp] hi/lo ----------------
__global__ void convert_wt(const float* __restrict__ W, bf16* __restrict__ Th,
                           bf16* __restrict__ Tl, int K, int N, int Kp)
{
    __shared__ float tile[32][33];
    const int n0 = blockIdx.x * 32, k0 = blockIdx.y * 32;
    const int tx = threadIdx.x, ty = threadIdx.y;  // 32 x 8
#pragma unroll
    for (int i = 0; i < 32; i += 8) {
        int k = k0 + ty + i;
        tile[ty + i][tx] = (k < K) ? W[k * N + n0 + tx] : 0.f;
    }
    __syncthreads();
#pragma unroll
    for (int i = 0; i < 32; i += 8) {
        int n = n0 + ty + i, k = k0 + tx;
        float v = tile[tx][ty + i];
        bf16 h, l; split_bf16(v, h, l);
        Th[n * Kp + k] = h;
        Tl[n * Kp + k] = l;
    }
}

// ---------------- build encoder input (split bf16) ----------------
__global__ void build_x1(const float* __restrict__ inp, const float* __restrict__ traj,
                         const float* __restrict__ mean, const float* __restrict__ stdv)
{
    int idx = blockIdx.x * blockDim.x + threadIdx.x;
    if (idx >= NBATCH * 256) return;
    int b = idx >> 8, c = idx & 255;
    float val;
    if (c < 55)       val = (inp[b * 55 + c] - mean[c]) / stdv[c];
    else if (c < 255) val = traj[b * 200 + c - 55];
    else              val = 0.f;
    bf16 h, l; split_bf16(val, h, l);
    g_X1h[idx] = h; g_X1l[idx] = l;
}

// ---------------- split-bf16 tensor-core GEMM ----------------
// C = relu(A @ W + bias), A [1024][Kp] hi/lo bf16, Wt [1024 n][Kp] hi/lo bf16,
// out split bf16 Ch/Cl [1024][1024]. Tile 64x64, 4 warps, 2-stage cp.async.
#define GST 24   // smem row stride (elems): conflict-free for ldmatrix + b32 LDS
__global__ __launch_bounds__(128) void gemm_mma(
    const bf16* __restrict__ Ah, const bf16* __restrict__ Al,
    const bf16* __restrict__ Bh, const bf16* __restrict__ Bl,
    const float* __restrict__ bias,
    bf16* __restrict__ Ch, bf16* __restrict__ Cl, int Kp)
{
    __shared__ bf16 sm[2][4][64][GST];
    const int tid = threadIdx.x;
    const int bm0 = blockIdx.y * 64, bn0 = blockIdx.x * 64;
    const int w = tid >> 5, lane = tid & 31;
    const int wm = (w >> 1) * 32, wn = (w & 1) * 32;
    const int g = lane >> 2, tig = lane & 3;

    float acc[2][4][4];
#pragma unroll
    for (int mt = 0; mt < 2; mt++)
#pragma unroll
        for (int nt = 0; nt < 4; nt++)
#pragma unroll
            for (int q = 0; q < 4; q++) acc[mt][nt][q] = 0.f;

    const bf16* srcs[4] = { Ah + (size_t)bm0 * Kp, Al + (size_t)bm0 * Kp,
                            Bh + (size_t)bn0 * Kp, Bl + (size_t)bn0 * Kp };
    const int r = tid >> 1, half = tid & 1;   // copy role: 64 rows x 2 halves

    const int KC = Kp >> 4;

#define ISSUE(chunk, buf)                                                         \
    {                                                                             \
        _Pragma("unroll")                                                         \
        for (int ci = 0; ci < 4; ci++) {                                          \
            const bf16* s = srcs[ci] + r * Kp + (chunk) * 16 + half * 8;          \
            uint32_t d = (uint32_t)__cvta_generic_to_shared(&sm[buf][ci][r][half * 8]); \
            asm volatile("cp.async.cg.shared.global [%0], [%1], 16;" :: "r"(d), "l"(s)); \
        }                                                                         \
    }

    ISSUE(0, 0);
    asm volatile("cp.async.commit_group;");

    const int arow = wm + (lane & 15);
    const int akoff = (lane >> 4) * 8;

    for (int c = 0; c < KC; c++) {
        if (c + 1 < KC) ISSUE(c + 1, (c + 1) & 1);
        asm volatile("cp.async.commit_group;");
        asm volatile("cp.async.wait_group 1;");
        __syncthreads();
        const int buf = c & 1;

        uint32_t aH[2][4], aL[2][4], bH[4][2], bL[4][2];
#pragma unroll
        for (int mt = 0; mt < 2; mt++) {
            uint32_t ad = (uint32_t)__cvta_generic_to_shared(&sm[buf][0][arow + mt * 16][akoff]);
            asm volatile("ldmatrix.sync.aligned.m8n8.x4.shared.b16 {%0,%1,%2,%3}, [%4];"
                : "=r"(aH[mt][0]), "=r"(aH[mt][1]), "=r"(aH[mt][2]), "=r"(aH[mt][3]) : "r"(ad));
            uint32_t ad2 = (uint32_t)__cvta_generic_to_shared(&sm[buf][1][arow + mt * 16][akoff]);
            asm volatile("ldmatrix.sync.aligned.m8n8.x4.shared.b16 {%0,%1,%2,%3}, [%4];"
                : "=r"(aL[mt][0]), "=r"(aL[mt][1]), "=r"(aL[mt][2]), "=r"(aL[mt][3]) : "r"(ad2));
        }
#pragma unroll
        for (int nt = 0; nt < 4; nt++) {
            int n = wn + nt * 8 + g;
            bH[nt][0] = *(const uint32_t*)&sm[buf][2][n][2 * tig];
            bH[nt][1] = *(const uint32_t*)&sm[buf][2][n][2 * tig + 8];
            bL[nt][0] = *(const uint32_t*)&sm[buf][3][n][2 * tig];
            bL[nt][1] = *(const uint32_t*)&sm[buf][3][n][2 * tig + 8];
        }

#define MMA(C, A, B0, B1)                                                          \
        asm volatile("mma.sync.aligned.m16n8k16.row.col.f32.bf16.bf16.f32 "        \
            "{%0,%1,%2,%3}, {%4,%5,%6,%7}, {%8,%9}, {%0,%1,%2,%3};"                \
            : "+f"(C[0]), "+f"(C[1]), "+f"(C[2]), "+f"(C[3])                       \
            : "r"(A[0]), "r"(A[1]), "r"(A[2]), "r"(A[3]), "r"(B0), "r"(B1));

#pragma unroll
        for (int mt = 0; mt < 2; mt++)
#pragma unroll
            for (int nt = 0; nt < 4; nt++) {
                MMA(acc[mt][nt], aH[mt], bH[nt][0], bH[nt][1]);
                MMA(acc[mt][nt], aH[mt], bL[nt][0], bL[nt][1]);
                MMA(acc[mt][nt], aL[mt], bH[nt][0], bH[nt][1]);
            }
        __syncthreads();
    }

    // epilogue: bias + relu + split store
#pragma unroll
    for (int mt = 0; mt < 2; mt++)
#pragma unroll
        for (int nt = 0; nt < 4; nt++) {
            int row = bm0 + wm + mt * 16 + g;
            int col = bn0 + wn + nt * 8 + 2 * tig;
            float b0 = bias[col], b1 = bias[col + 1];
#pragma unroll
            for (int hrow = 0; hrow < 2; hrow++) {
                float v0 = fmaxf(acc[mt][nt][hrow * 2 + 0] + b0, 0.f);
                float v1 = fmaxf(acc[mt][nt][hrow * 2 + 1] + b1, 0.f);
                bf16 h0, l0, h1, l1;
                split_bf16(v0, h0, l0);
                split_bf16(v1, h1, l1);
                size_t off = (size_t)(row + hrow * 8) * 1024 + col;
                __nv_bfloat162 hh; hh.x = h0; hh.y = h1;
                __nv_bfloat162 ll; ll.x = l0; ll.y = l1;
                *(__nv_bfloat162*)&Ch[off] = hh;
                *(__nv_bfloat162*)&Cl[off] = ll;
            }
        }
#undef MMA
#undef ISSUE
}

// ---------------- mu/logvar/z + decoder input ----------------
__global__ __launch_bounds__(128) void zdec_kernel(
    const float* __restrict__ wmu, const float* __restrict__ bmu,
    const float* __restrict__ wlv, const float* __restrict__ blv,
    const float* __restrict__ eps, const float* __restrict__ inp,
    const float* __restrict__ mean, const float* __restrict__ stdv)
{
    __shared__ float sred[4];
    __shared__ float zz[2];
    const int b = blockIdx.x, tid = threadIdx.x;
    const int warp = tid >> 5, lane = tid & 31;
    const bf16* hh = g_H2h + b * 1024;
    const bf16* hl = g_H2l + b * 1024;
    const float* w = (warp < 2) ? wmu : wlv;
    const int c = warp & 1;
    float s = 0.f;
    for (int k = lane; k < 1024; k += 32) {
        float hv = __bfloat162float(hh[k]) + __bfloat162float(hl[k]);
        s = fmaf(hv, w[k * 2 + c], s);
    }
#pragma unroll
    for (int off = 16; off; off >>= 1) s += __shfl_down_sync(0xffffffffu, s, off);
    if (lane == 0) sred[warp] = s;
    __syncthreads();
    if (tid < 2) {
        float mu = sred[tid] + bmu[tid];
        float lv = sred[2 + tid] + blv[tid];
        zz[tid] = mu + expf(0.5f * lv) * eps[b * 2 + tid];
    }
    __syncthreads();
    if (tid < 64) {
        float val;
        if (tid < 2)       val = zz[tid];
        else if (tid < 57) val = (inp[b * 55 + tid - 2] - mean[tid - 2]) / stdv[tid - 2];
        else               val = 0.f;
        bf16 h, l; split_bf16(val, h, l);
        g_X2h[b * 64 + tid] = h;
        g_X2l[b * 64 + tid] = l;
    }
}

// ---------------- final 8-wide projection ----------------
__global__ __launch_bounds__(256) void nn8_kernel(const float* __restrict__ w3,
                                                  const float* __restrict__ b3)
{
    const int b = blockIdx.x, tid = threadIdx.x;
    const int warp = tid >> 5, lane = tid & 31;
    const bf16* hh = g_H2h + b * 1024;
    const bf16* hl = g_H2l + b * 1024;
    float s = 0.f;
    for (int k = lane; k < 1024; k += 32) {
        float hv = __bfloat162float(hh[k]) + __bfloat162float(hl[k]);
        s = fmaf(hv, w3[k * 8 + warp], s);
    }
#pragma unroll
    for (int off = 16; off; off >>= 1) s += __shfl_down_sync(0xffffffffu, s, off);
    if (lane == 0) g_nn[b * 8 + warp] = s + b3[warp];
}

// ---------------- solver: 20 ADMM iterations, 1 block / batch row ----------------
__global__ __launch_bounds__(128) void solver_kernel(
    const float* __restrict__ P, const float* __restrict__ Pd, const float* __restrict__ Pdd,
    const float* __restrict__ ise, const float* __restrict__ yub, const float* __restrict__ ylb,
    const float* __restrict__ inp, float* __restrict__ out)
{
    __shared__ float sP[1100], sPd[1100], sPdd[1100];
    __shared__ float v[700];
    __shared__ float red[77];
    __shared__ float cx[11], cy[11], lxs[11], lys[11], cxb[11], cyb[11];
    __shared__ float ex[11], ey[11], linx[11], liny[11];
    __shared__ float sMx[121], sMy[121];
    __shared__ float sI2x[154], sI2y[165];
    __shared__ float sobs[40], snn[8], scal[4];

    const int b = blockIdx.x, tid = threadIdx.x;

    for (int e = tid; e < 1100; e += 128) { sP[e] = P[e]; sPd[e] = Pd[e]; sPdd[e] = Pdd[e]; }
    for (int e = tid; e < 121; e += 128) { sMx[e] = g_Mx[e]; sMy[e] = g_My[e]; }
    for (int e = tid; e < 154; e += 128) sI2x[e] = g_inv2x[e];
    for (int e = tid; e < 165; e += 128) sI2y[e] = g_inv2y[e];
    if (tid < 40) {
        int o = tid >> 2, c = tid & 3;
        sobs[tid] = inp[b * 55 + 5 + 5 * o + c];
    }
    if (tid < 8) snn[tid] = g_nn[b * 8 + tid];
    if (tid == 0) { scal[0] = yub[b]; scal[1] = ylb[b]; scal[2] = ise[b * 4 + 2]; scal[3] = ise[b * 4 + 3]; }
    __syncthreads();

    if (tid < 11) {
        float sx_ = 0.f, sy_ = 0.f;
#pragma unroll
        for (int g = 0; g < 4; g++) {
            sx_ = fmaf(snn[g],     g_GAvd[g * 11 + tid], sx_);
            sy_ = fmaf(snn[4 + g], g_GApd[g * 11 + tid], sy_);
        }
        linx[tid] = 20.f * sx_;
        liny[tid] = 20.f * sy_;
    }
    __syncthreads();
    if (tid < 11) {
        int i = tid;
        float cxv = g_inv1x[i * 14 + 12] * scal[2];
        float cyv = g_inv1y[i * 15 + 12] * scal[3];
#pragma unroll
        for (int j = 0; j < 11; j++) {
            cxv = fmaf(-g_inv1x[i * 14 + j], linx[j], cxv);
            cyv = fmaf(-g_inv1y[i * 15 + j], liny[j], cyv);
        }
        cxb[i] = cxv; cyb[i] = cyv; cx[i] = cxv; cy[i] = cyv;
        lxs[i] = 0.f; lys[i] = 0.f;
        ex[i] = sI2x[i * 14 + 12] * scal[2];
        ey[i] = sI2y[i * 15 + 12] * scal[3];
    }

    for (int it = 0; it < 20; it++) {
        __syncthreads();
        if (tid < 100) {
            const int t = tid;
            float x = 0.f, xd = 0.f, xdd = 0.f, y = 0.f, yd = 0.f, ydd = 0.f;
#pragma unroll
            for (int j = 0; j < 11; j++) {
                float a = cx[j], c = cy[j];
                float p = sP[t * 11 + j], pd = sPd[t * 11 + j], pdd = sPdd[t * 11 + j];
                x = fmaf(a, p, x);  xd = fmaf(a, pd, xd);  xdd = fmaf(a, pdd, xdd);
                y = fmaf(c, p, y);  yd = fmaf(c, pd, yd);  ydd = fmaf(c, pdd, ydd);
            }
            const float tt = (15.0f / 99.0f) * t;
            float Rx = 0.f, Ry = 0.f;
#pragma unroll
            for (int o = 0; o < 10; o++) {
                float wc = x - fmaf(sobs[o * 4 + 2], tt, sobs[o * 4 + 0]);
                float ws = y - fmaf(sobs[o * 4 + 3], tt, sobs[o * 4 + 1]);
                float aw = AOBS * ws, bw = BOBS * wc;
                float q = fmaf(aw, aw, bw * bw);
                float rinv = rsqrtf(fmaxf(q, 1e-30f));
                float ca = bw * rinv, sa = aw * rinv;
                float c1 = fmaf(64.f * ca, ca, 17.64f * sa * sa);
                float c2 = fmaf(8.f * wc, ca, 4.2f * ws * sa);
                float d = fmaxf(1.f, __fdividef(c2, c1));
                Rx += wc - 8.f * d * ca;
                Ry += ws - 4.2f * d * sa;
            }
            float rv2 = fmaf(xd, xd, yd * yd);
            float dv = fminf(fmaxf(sqrtf(rv2), 0.1f), 30.f);
            float fv = 1.f - dv * rsqrtf(fmaxf(rv2, 1e-30f));
            float ra2 = fmaf(xdd, xdd, ydd * ydd);
            float da = fminf(sqrtf(ra2), 8.f);
            float fa = 1.f - da * rsqrtf(fmaxf(ra2, 1e-30f));
            float ycl = fminf(fmaxf(y, scal[1]), scal[0]);
            v[t]       = Rx;
            v[100 + t] = Ry;
            v[200 + t] = xdd * fa;
            v[300 + t] = ydd * fa;
            v[400 + t] = xd * fv;
            v[500 + t] = yd * fv;
            v[600 + t] = y - ycl;
        }
        __syncthreads();
        if (tid < 77) {
            const int q = tid / 11, j = tid % 11;
            const float* basis = (q == 2 || q == 3) ? sPdd : (q == 4 || q == 5) ? sPd : sP;
            const float* vv = v + q * 100;
            float s = 0.f;
            for (int t = 0; t < 100; t++) s = fmaf(vv[t], basis[t * 11 + j], s);
            red[tid] = s;
        }
        __syncthreads();
        if (tid < 11) {
            const int j = tid;
            float Dx = 100.f * (red[j] + red[22 + j] + red[44 + j]);
            float Dy = 100.f * (red[11 + j] + red[33 + j] + red[55 + j] + red[66 + j]);
            float lxn = lxs[j] - Dx, lyn = lys[j] - Dy;
            lxs[j] = lxn; lys[j] = lyn;
            float mx = 0.f, my = 0.f;
#pragma unroll
            for (int i = 0; i < 11; i++) {
                mx = fmaf(cx[i], sMx[i * 11 + j], mx);
                my = fmaf(cy[i], sMy[i * 11 + j], my);
            }
            linx[j] = -lxn + Dx - cxb[j] - mx;
            liny[j] = -lyn + Dy - cyb[j] - my;
        }
        __syncthreads();
        if (tid < 22) {
            const int i = tid % 11;
            if (tid < 11) {
                float s = ex[i];
#pragma unroll
                for (int j = 0; j < 11; j++) s = fmaf(-sI2x[i * 14 + j], linx[j], s);
                cx[i] = s;
            } else {
                float s = ey[i];
#pragma unroll
                for (int j = 0; j < 11; j++) s = fmaf(-sI2y[i * 15 + j], liny[j], s);
                cy[i] = s;
            }
        }
    }
    __syncthreads();
    if (tid < 22) out[b * 22 + tid] = (tid < 11) ? cx[tid] : cy[tid - 11];
}

// ---------------- launch ----------------
extern "C" void kernel_launch(void* const* d_in, const int* in_sizes, int n_in,
                              void* d_out, int out_size)
{
    const float* inp  = (const float*)d_in[0];
    const float* ise  = (const float*)d_in[1];
    const float* traj = (const float*)d_in[2];
    const float* yub  = (const float*)d_in[3];
    const float* ylb  = (const float*)d_in[4];
    const float* eps  = (const float*)d_in[5];
    const float* ew1  = (const float*)d_in[6];
    const float* eb1  = (const float*)d_in[7];
    const float* ew2  = (const float*)d_in[8];
    const float* eb2  = (const float*)d_in[9];
    const float* wmu  = (const float*)d_in[10];
    const float* bmu  = (const float*)d_in[11];
    const float* wlv  = (const float*)d_in[12];
    const float* blv  = (const float*)d_in[13];
    const float* dw1  = (const float*)d_in[14];
    const float* db1  = (const float*)d_in[15];
    const float* dw2  = (const float*)d_in[16];
    const float* db2  = (const float*)d_in[17];
    const float* dw3  = (const float*)d_in[18];
    const float* db3  = (const float*)d_in[19];
    const float* P    = (const float*)d_in[20];
    const float* Pd   = (const float*)d_in[21];
    const float* Pdd  = (const float*)d_in[22];
    const float* imean = (const float*)d_in[23];
    const float* istd  = (const float*)d_in[24];
    float* out = (float*)d_out;

    bf16 *pX1h, *pX1l, *pH1h, *pH1l, *pH2h, *pH2l, *pX2h, *pX2l;
    bf16 *pT1h, *pT1l, *pT2h, *pT2l, *pT3h, *pT3l, *pT4h, *pT4l;
    cudaGetSymbolAddress((void**)&pX1h, g_X1h); cudaGetSymbolAddress((void**)&pX1l, g_X1l);
    cudaGetSymbolAddress((void**)&pH1h, g_H1h); cudaGetSymbolAddress((void**)&pH1l, g_H1l);
    cudaGetSymbolAddress((void**)&pH2h, g_H2h); cudaGetSymbolAddress((void**)&pH2l, g_H2l);
    cudaGetSymbolAddress((void**)&pX2h, g_X2h); cudaGetSymbolAddress((void**)&pX2l, g_X2l);
    cudaGetSymbolAddress((void**)&pT1h, g_T1h); cudaGetSymbolAddress((void**)&pT1l, g_T1l);
    cudaGetSymbolAddress((void**)&pT2h, g_T2h); cudaGetSymbolAddress((void**)&pT2l, g_T2l);
    cudaGetSymbolAddress((void**)&pT3h, g_T3h); cudaGetSymbolAddress((void**)&pT3l, g_T3l);
    cudaGetSymbolAddress((void**)&pT4h, g_T4h); cudaGetSymbolAddress((void**)&pT4l, g_T4l);

    setup_kernel<<<4, 128>>>(P, Pd, Pdd);

    dim3 tb(32, 8);
    convert_wt<<<dim3(32, 8),  tb>>>(ew1, pT1h, pT1l, 255,  1024, 256);
    convert_wt<<<dim3(32, 32), tb>>>(ew2, pT2h, pT2l, 1024, 1024, 1024);
    convert_wt<<<dim3(32, 2),  tb>>>(dw1, pT3h, pT3l, 57,   1024, 64);
    convert_wt<<<dim3(32, 32), tb>>>(dw2, pT4h, pT4l, 1024, 1024, 1024);

    build_x1<<<(NBATCH * 256) / 256, 256>>>(inp, traj, imean, istd);

    dim3 gg(16, 16);
    gemm_mma<<<gg, 128>>>(pX1h, pX1l, pT1h, pT1l, eb1, pH1h, pH1l, 256);
    gemm_mma<<<gg, 128>>>(pH1h, pH1l, pT2h, pT2l, eb2, pH2h, pH2l, 1024);
    zdec_kernel<<<NBATCH, 128>>>(wmu, bmu, wlv, blv, eps, inp, imean, istd);
    gemm_mma<<<gg, 128>>>(pX2h, pX2l, pT3h, pT3l, db1, pH1h, pH1l, 64);
    gemm_mma<<<gg, 128>>>(pH1h, pH1l, pT4h, pT4l, db2, pH2h, pH2l, 1024);
    nn8_kernel<<<NBATCH, 256>>>(dw3, db3);
    solver_kernel<<<NBATCH, 128>>>(P, Pd, Pdd, ise, yub, ylb, inp, out);
}

// round 12
// speedup vs baseline: 1.4796x; 1.0183x over previous
#include <cuda_runtime.h>
#include <cuda_bf16.h>
#include <math.h>
#include <stdint.h>

#define NBATCH 1024
#define NUMT   100
#define AOBS   8.0f
#define BOBS   4.2f

typedef __nv_bfloat16 bf16;

// ---------------- device scratch ----------------
__device__ bf16 g_X1h[NBATCH * 256], g_X1l[NBATCH * 256];
__device__ bf16 g_H1h[NBATCH * 1024], g_H1l[NBATCH * 1024];
__device__ bf16 g_H2h[NBATCH * 1024], g_H2l[NBATCH * 1024];
__device__ bf16 g_X2h[NBATCH * 64], g_X2l[NBATCH * 64];
__device__ float g_nn[NBATCH * 8];

// transposed + split weights: Wt[n][kp]
__device__ bf16 g_T1h[1024 * 256],  g_T1l[1024 * 256];
__device__ bf16 g_T2h[1024 * 1024], g_T2l[1024 * 1024];
__device__ bf16 g_T3h[1024 * 64],   g_T3l[1024 * 64];
__device__ bf16 g_T4h[1024 * 1024], g_T4l[1024 * 1024];

__device__ float g_inv1x[11 * 14];
__device__ float g_inv1y[11 * 15];
__device__ float g_inv2x[11 * 14];
__device__ float g_inv2y[11 * 15];
__device__ float g_Mx[121];
__device__ float g_My[121];
__device__ float g_GAvd[4 * 11];
__device__ float g_GApd[4 * 11];

// ---------------- setup: Grams + KKT inverses (fp64 Gauss-Jordan) ----------------
__global__ __launch_bounds__(128) void setup_kernel(
    const float* __restrict__ P, const float* __restrict__ Pd, const float* __restrict__ Pdd)
{
    __shared__ double SP[121], SD[121], SDD[121], SAV[121], SAP[121];
    __shared__ double M[15 * 30];
    __shared__ double fac[15];
    __shared__ double spinv;
    __shared__ int spiv;

    const int tid = threadIdx.x;
    const int m = blockIdx.x;
    const double KD = 2.0 * sqrt(20.0);

    for (int e = tid; e < 121; e += 128) {
        int i = e / 11, j = e % 11;
        double sp = 0, sd = 0, sdd = 0, sav = 0, sap = 0;
        for (int t = 0; t < NUMT; t++) {
            double pi = P[t * 11 + i],  pj = P[t * 11 + j];
            double di = Pd[t * 11 + i], dj = Pd[t * 11 + j];
            double ai = Pdd[t * 11 + i], aj = Pdd[t * 11 + j];
            sp += pi * pj; sd += di * dj; sdd += ai * aj;
            double avi = ai - 20.0 * di, avj = aj - 20.0 * dj;
            sav += avi * avj;
            double api = ai - 20.0 * pi - KD * di, apj = aj - 20.0 * pj - KD * dj;
            sap += api * apj;
        }
        SP[e] = sp; SD[e] = sd; SDD[e] = sdd; SAV[e] = sav; SAP[e] = sap;
    }
    __syncthreads();

    const int n = (m == 0 || m == 2) ? 14 : 15;
    const int n2 = 2 * n;

    for (int e = tid; e < n * n2; e += 128) {
        int i = e / n2, j = e % n2;
        double val;
        if (j >= n) {
            val = ((j - n) == i) ? 1.0 : 0.0;
        } else if (i < 11 && j < 11) {
            int e2 = i * 11 + j;
            if (m == 0)      val = SDD[e2] + SAV[e2];
            else if (m == 1) val = SDD[e2] + SAP[e2];
            else {
                val = 1000.0 * SP[e2] + 100.0 * (SDD[e2] + SD[e2]);
                if (i == j) val += 1.0;
                if (m == 3) val += 200.0 * SP[e2];
            }
        } else if (i >= 11 && j < 11) {
            int r = i - 11;
            val = (r == 0) ? (double)P[j] : (r == 1) ? (double)Pd[j] :
                  (r == 2) ? (double)Pdd[j] : (double)Pd[99 * 11 + j];
        } else if (j >= 11 && i < 11) {
            int r = j - 11;
            val = (r == 0) ? (double)P[i] : (r == 1) ? (double)Pd[i] :
                  (r == 2) ? (double)Pdd[i] : (double)Pd[99 * 11 + i];
        } else val = 0.0;
        M[i * n2 + j] = val;
    }
    __syncthreads();

    for (int k = 0; k < n; k++) {
        if (tid == 0) {
            int piv = k; double best = fabs(M[k * n2 + k]);
            for (int r = k + 1; r < n; r++) {
                double vv = fabs(M[r * n2 + k]);
                if (vv > best) { best = vv; piv = r; }
            }
            spiv = piv;
        }
        __syncthreads();
        int piv = spiv;
        if (piv != k)
            for (int j = tid; j < n2; j += 128) {
                double t = M[k * n2 + j]; M[k * n2 + j] = M[piv * n2 + j]; M[piv * n2 + j] = t;
            }
        __syncthreads();
        if (tid == 0) spinv = 1.0 / M[k * n2 + k];
        __syncthreads();
        for (int j = tid; j < n2; j += 128) M[k * n2 + j] *= spinv;
        __syncthreads();
        for (int i = tid; i < n; i += 128) fac[i] = M[i * n2 + k];
        __syncthreads();
        for (int e = tid; e < n * n2; e += 128) {
            int i = e / n2, j = e % n2;
            if (i != k) M[i * n2 + j] -= fac[i] * M[k * n2 + j];
        }
        __syncthreads();
    }

    float* dst = (m == 0) ? g_inv1x : (m == 1) ? g_inv1y : (m == 2) ? g_inv2x : g_inv2y;
    for (int e = tid; e < 11 * n; e += 128) {
        int i = e / n, j = e % n;
        dst[e] = (float)M[i * n2 + n + j];
    }
    if (m == 0) {
        for (int e = tid; e < 121; e += 128) {
            float mx = (float)(1000.0 * SP[e] + 100.0 * (SD[e] + SDD[e]));
            g_Mx[e] = mx;
            g_My[e] = mx + (float)(200.0 * SP[e]);
        }
        for (int e = tid; e < 44; e += 128) {
            int g = e / 11, j = e % 11;
            double sv = 0, sp2 = 0;
            for (int t = 25 * g; t < 25 * g + 25; t++) {
                sv  += (double)Pdd[t * 11 + j] - 20.0 * Pd[t * 11 + j];
                sp2 += (double)Pdd[t * 11 + j] - 20.0 * P[t * 11 + j] - KD * Pd[t * 11 + j];
            }
            g_GAvd[e] = (float)sv;
            g_GApd[e] = (float)sp2;
        }
    }
}

// ---------------- split helper ----------------
__device__ __forceinline__ void split_bf16(float v, bf16& h, bf16& l) {
    h = __float2bfloat16(v);
    l = __float2bfloat16(v - __bfloat162float(h));
}

// ---------------- weight transpose + split ----------------
__global__ void convert_wt(const float* __restrict__ W, bf16* __restrict__ Th,
                           bf16* __restrict__ Tl, int K, int N, int Kp)
{
    __shared__ float tile[32][33];
    const int n0 = blockIdx.x * 32, k0 = blockIdx.y * 32;
    const int tx = threadIdx.x, ty = threadIdx.y;  // 32 x 8
#pragma unroll
    for (int i = 0; i < 32; i += 8) {
        int k = k0 + ty + i;
        tile[ty + i][tx] = (k < K) ? W[k * N + n0 + tx] : 0.f;
    }
    __syncthreads();
#pragma unroll
    for (int i = 0; i < 32; i += 8) {
        int n = n0 + ty + i, k = k0 + tx;
        float v = tile[tx][ty + i];
        bf16 h, l; split_bf16(v, h, l);
        Th[n * Kp + k] = h;
        Tl[n * Kp + k] = l;
    }
}

// ---------------- build encoder input (split bf16) ----------------
__global__ void build_x1(const float* __restrict__ inp, const float* __restrict__ traj,
                         const float* __restrict__ mean, const float* __restrict__ stdv)
{
    int idx = blockIdx.x * blockDim.x + threadIdx.x;
    if (idx >= NBATCH * 256) return;
    int b = idx >> 8, c = idx & 255;
    float val;
    if (c < 55)       val = (inp[b * 55 + c] - mean[c]) / stdv[c];
    else if (c < 255) val = traj[b * 200 + c - 55];
    else              val = 0.f;
    bf16 h, l; split_bf16(val, h, l);
    g_X1h[idx] = h; g_X1l[idx] = l;
}

// ---------------- split-bf16 tensor-core GEMM ----------------
// 64x64 CTA tile, 256 threads (8 warps, warp tile 16x32), 2-stage cp.async.
#define GST 24
__global__ __launch_bounds__(256) void gemm_mma(
    const bf16* __restrict__ Ah, const bf16* __restrict__ Al,
    const bf16* __restrict__ Bh, const bf16* __restrict__ Bl,
    const float* __restrict__ bias,
    bf16* __restrict__ Ch, bf16* __restrict__ Cl, int Kp)
{
    __shared__ bf16 sm[2][4][64][GST];
    const int tid = threadIdx.x;
    const int bm0 = blockIdx.y * 64, bn0 = blockIdx.x * 64;
    const int w = tid >> 5, lane = tid & 31;
    const int wm = (w >> 1) * 16, wn = (w & 1) * 32;
    const int g = lane >> 2, tig = lane & 3;

    float acc[4][4];
#pragma unroll
    for (int nt = 0; nt < 4; nt++)
#pragma unroll
        for (int q = 0; q < 4; q++) acc[nt][q] = 0.f;

    const bf16* srcs[4] = { Ah + (size_t)bm0 * Kp, Al + (size_t)bm0 * Kp,
                            Bh + (size_t)bn0 * Kp, Bl + (size_t)bn0 * Kp };

    const int KC = Kp >> 4;

#define ISSUE(chunk, buf)                                                         \
    {                                                                             \
        _Pragma("unroll")                                                         \
        for (int s = 0; s < 2; s++) {                                             \
            int slot = tid + 256 * s;                                             \
            int ci = slot >> 7, rem = slot & 127;                                 \
            int rr = rem >> 1, hf = rem & 1;                                      \
            const bf16* sp_ = srcs[ci] + rr * Kp + (chunk) * 16 + hf * 8;         \
            uint32_t d = (uint32_t)__cvta_generic_to_shared(&sm[buf][ci][rr][hf * 8]); \
            asm volatile("cp.async.cg.shared.global [%0], [%1], 16;" :: "r"(d), "l"(sp_)); \
        }                                                                         \
    }

    ISSUE(0, 0);
    asm volatile("cp.async.commit_group;");

    const int arow = wm + (lane & 15);
    const int akoff = (lane >> 4) * 8;

    for (int c = 0; c < KC; c++) {
        if (c + 1 < KC) ISSUE(c + 1, (c + 1) & 1);
        asm volatile("cp.async.commit_group;");
        asm volatile("cp.async.wait_group 1;");
        __syncthreads();
        const int buf = c & 1;

        uint32_t aH[4], aL[4], bH[4][2], bL[4][2];
        {
            uint32_t ad = (uint32_t)__cvta_generic_to_shared(&sm[buf][0][arow][akoff]);
            asm volatile("ldmatrix.sync.aligned.m8n8.x4.shared.b16 {%0,%1,%2,%3}, [%4];"
                : "=r"(aH[0]), "=r"(aH[1]), "=r"(aH[2]), "=r"(aH[3]) : "r"(ad));
            uint32_t ad2 = (uint32_t)__cvta_generic_to_shared(&sm[buf][1][arow][akoff]);
            asm volatile("ldmatrix.sync.aligned.m8n8.x4.shared.b16 {%0,%1,%2,%3}, [%4];"
                : "=r"(aL[0]), "=r"(aL[1]), "=r"(aL[2]), "=r"(aL[3]) : "r"(ad2));
        }
#pragma unroll
        for (int nt = 0; nt < 4; nt++) {
            int n = wn + nt * 8 + g;
            bH[nt][0] = *(const uint32_t*)&sm[buf][2][n][2 * tig];
            bH[nt][1] = *(const uint32_t*)&sm[buf][2][n][2 * tig + 8];
            bL[nt][0] = *(const uint32_t*)&sm[buf][3][n][2 * tig];
            bL[nt][1] = *(const uint32_t*)&sm[buf][3][n][2 * tig + 8];
        }

#define MMA(C, A, B0, B1)                                                          \
        asm volatile("mma.sync.aligned.m16n8k16.row.col.f32.bf16.bf16.f32 "        \
            "{%0,%1,%2,%3}, {%4,%5,%6,%7}, {%8,%9}, {%0,%1,%2,%3};"                \
            : "+f"(C[0]), "+f"(C[1]), "+f"(C[2]), "+f"(C[3])                       \
            : "r"(A[0]), "r"(A[1]), "r"(A[2]), "r"(A[3]), "r"(B0), "r"(B1));

#pragma unroll
        for (int nt = 0; nt < 4; nt++) {
            MMA(acc[nt], aH, bH[nt][0], bH[nt][1]);
            MMA(acc[nt], aH, bL[nt][0], bL[nt][1]);
            MMA(acc[nt], aL, bH[nt][0], bH[nt][1]);
        }
        __syncthreads();
    }

    // epilogue: bias + relu + split store
#pragma unroll
    for (int nt = 0; nt < 4; nt++) {
        int row = bm0 + wm + g;
        int col = bn0 + wn + nt * 8 + 2 * tig;
        float b0 = bias[col], b1 = bias[col + 1];
#pragma unroll
        for (int hrow = 0; hrow < 2; hrow++) {
            float v0 = fmaxf(acc[nt][hrow * 2 + 0] + b0, 0.f);
            float v1 = fmaxf(acc[nt][hrow * 2 + 1] + b1, 0.f);
            bf16 h0, l0, h1, l1;
            split_bf16(v0, h0, l0);
            split_bf16(v1, h1, l1);
            size_t off = (size_t)(row + hrow * 8) * 1024 + col;
            __nv_bfloat162 hh; hh.x = h0; hh.y = h1;
            __nv_bfloat162 ll; ll.x = l0; ll.y = l1;
            *(__nv_bfloat162*)&Ch[off] = hh;
            *(__nv_bfloat162*)&Cl[off] = ll;
        }
    }
#undef MMA
#undef ISSUE
}

// ---------------- mu/logvar/z + decoder input ----------------
__global__ __launch_bounds__(128) void zdec_kernel(
    const float* __restrict__ wmu, const float* __restrict__ bmu,
    const float* __restrict__ wlv, const float* __restrict__ blv,
    const float* __restrict__ eps, const float* __restrict__ inp,
    const float* __restrict__ mean, const float* __restrict__ stdv)
{
    __shared__ float sred[4];
    __shared__ float zz[2];
    const int b = blockIdx.x, tid = threadIdx.x;
    const int warp = tid >> 5, lane = tid & 31;
    const bf16* hh = g_H2h + b * 1024;
    const bf16* hl = g_H2l + b * 1024;
    const float* w = (warp < 2) ? wmu : wlv;
    const int c = warp & 1;
    float s = 0.f;
    for (int k = lane; k < 1024; k += 32) {
        float hv = __bfloat162float(hh[k]) + __bfloat162float(hl[k]);
        s = fmaf(hv, w[k * 2 + c], s);
    }
#pragma unroll
    for (int off = 16; off; off >>= 1) s += __shfl_down_sync(0xffffffffu, s, off);
    if (lane == 0) sred[warp] = s;
    __syncthreads();
    if (tid < 2) {
        float mu = sred[tid] + bmu[tid];
        float lv = sred[2 + tid] + blv[tid];
        zz[tid] = mu + expf(0.5f * lv) * eps[b * 2 + tid];
    }
    __syncthreads();
    if (tid < 64) {
        float val;
        if (tid < 2)       val = zz[tid];
        else if (tid < 57) val = (inp[b * 55 + tid - 2] - mean[tid - 2]) / stdv[tid - 2];
        else               val = 0.f;
        bf16 h, l; split_bf16(val, h, l);
        g_X2h[b * 64 + tid] = h;
        g_X2l[b * 64 + tid] = l;
    }
}

// ---------------- final 8-wide projection ----------------
__global__ __launch_bounds__(256) void nn8_kernel(const float* __restrict__ w3,
                                                  const float* __restrict__ b3)
{
    const int b = blockIdx.x, tid = threadIdx.x;
    const int warp = tid >> 5, lane = tid & 31;
    const bf16* hh = g_H2h + b * 1024;
    const bf16* hl = g_H2l + b * 1024;
    float s = 0.f;
    for (int k = lane; k < 1024; k += 32) {
        float hv = __bfloat162float(hh[k]) + __bfloat162float(hl[k]);
        s = fmaf(hv, w3[k * 8 + warp], s);
    }
#pragma unroll
    for (int off = 16; off; off >>= 1) s += __shfl_down_sync(0xffffffffu, s, off);
    if (lane == 0) g_nn[b * 8 + warp] = s + b3[warp];
}

// ---------------- solver: 20 ADMM iterations, 1 block / batch row ----------------
// basis in transposed [j][t] layout for float4 reductions
__global__ __launch_bounds__(128) void solver_kernel(
    const float* __restrict__ P, const float* __restrict__ Pd, const float* __restrict__ Pdd,
    const float* __restrict__ ise, const float* __restrict__ yub, const float* __restrict__ ylb,
    const float* __restrict__ inp, float* __restrict__ out)
{
    __shared__ float sPT[3][1100];     // [array][j*100 + t]
    __shared__ float v[700];
    __shared__ float red[77];
    __shared__ float cx[11], cy[11], lxs[11], lys[11], cxb[11], cyb[11];
    __shared__ float ex[11], ey[11], linx[11], liny[11];
    __shared__ float sMx[121], sMy[121];
    __shared__ float sI2x[154], sI2y[165];
    __shared__ float sobs[40], snn[8], scal[4];

    const int b = blockIdx.x, tid = threadIdx.x;

    for (int e = tid; e < 1100; e += 128) {
        int t = e / 11, j = e % 11;
        sPT[0][j * 100 + t] = P[e];
        sPT[1][j * 100 + t] = Pd[e];
        sPT[2][j * 100 + t] = Pdd[e];
    }
    for (int e = tid; e < 121; e += 128) { sMx[e] = g_Mx[e]; sMy[e] = g_My[e]; }
    for (int e = tid; e < 154; e += 128) sI2x[e] = g_inv2x[e];
    for (int e = tid; e < 165; e += 128) sI2y[e] = g_inv2y[e];
    if (tid < 40) {
        int o = tid >> 2, c = tid & 3;
        sobs[tid] = inp[b * 55 + 5 + 5 * o + c];
    }
    if (tid < 8) snn[tid] = g_nn[b * 8 + tid];
    if (tid == 0) { scal[0] = yub[b]; scal[1] = ylb[b]; scal[2] = ise[b * 4 + 2]; scal[3] = ise[b * 4 + 3]; }
    __syncthreads();

    if (tid < 11) {
        float sx_ = 0.f, sy_ = 0.f;
#pragma unroll
        for (int g = 0; g < 4; g++) {
            sx_ = fmaf(snn[g],     g_GAvd[g * 11 + tid], sx_);
            sy_ = fmaf(snn[4 + g], g_GApd[g * 11 + tid], sy_);
        }
        linx[tid] = 20.f * sx_;
        liny[tid] = 20.f * sy_;
    }
    __syncthreads();
    if (tid < 11) {
        int i = tid;
        float cxv = g_inv1x[i * 14 + 12] * scal[2];
        float cyv = g_inv1y[i * 15 + 12] * scal[3];
#pragma unroll
        for (int j = 0; j < 11; j++) {
            cxv = fmaf(-g_inv1x[i * 14 + j], linx[j], cxv);
            cyv = fmaf(-g_inv1y[i * 15 + j], liny[j], cyv);
        }
        cxb[i] = cxv; cyb[i] = cyv; cx[i] = cxv; cy[i] = cyv;
        lxs[i] = 0.f; lys[i] = 0.f;
        ex[i] = sI2x[i * 14 + 12] * scal[2];
        ey[i] = sI2y[i * 15 + 12] * scal[3];
    }

    for (int it = 0; it < 20; it++) {
        __syncthreads();
        if (tid < 100) {
            const int t = tid;
            float x = 0.f, xd = 0.f, xdd = 0.f, y = 0.f, yd = 0.f, ydd = 0.f;
#pragma unroll
            for (int j = 0; j < 11; j++) {
                float a = cx[j], c = cy[j];
                float p = sPT[0][j * 100 + t], pd = sPT[1][j * 100 + t], pdd = sPT[2][j * 100 + t];
                x = fmaf(a, p, x);  xd = fmaf(a, pd, xd);  xdd = fmaf(a, pdd, xdd);
                y = fmaf(c, p, y);  yd = fmaf(c, pd, yd);  ydd = fmaf(c, pdd, ydd);
            }
            const float tt = (15.0f / 99.0f) * t;
            float Rx = 0.f, Ry = 0.f;
#pragma unroll
            for (int o = 0; o < 10; o++) {
                float wc = x - fmaf(sobs[o * 4 + 2], tt, sobs[o * 4 + 0]);
                float ws = y - fmaf(sobs[o * 4 + 3], tt, sobs[o * 4 + 1]);
                float aw = AOBS * ws, bw = BOBS * wc;
                float q = fmaf(aw, aw, bw * bw);
                float rinv = rsqrtf(fmaxf(q, 1e-30f));
                float ca = bw * rinv, sa = aw * rinv;
                float c1 = fmaf(64.f * ca, ca, 17.64f * sa * sa);
                float c2 = fmaf(8.f * wc, ca, 4.2f * ws * sa);
                float d = fmaxf(1.f, __fdividef(c2, c1));
                Rx += wc - 8.f * d * ca;
                Ry += ws - 4.2f * d * sa;
            }
            float rv2 = fmaf(xd, xd, yd * yd);
            float dv = fminf(fmaxf(sqrtf(rv2), 0.1f), 30.f);
            float fv = 1.f - dv * rsqrtf(fmaxf(rv2, 1e-30f));
            float ra2 = fmaf(xdd, xdd, ydd * ydd);
            float da = fminf(sqrtf(ra2), 8.f);
            float fa = 1.f - da * rsqrtf(fmaxf(ra2, 1e-30f));
            float ycl = fminf(fmaxf(y, scal[1]), scal[0]);
            v[t]       = Rx;
            v[100 + t] = Ry;
            v[200 + t] = xdd * fa;
            v[300 + t] = ydd * fa;
            v[400 + t] = xd * fv;
            v[500 + t] = yd * fv;
            v[600 + t] = y - ycl;
        }
        __syncthreads();
        if (tid < 77) {
            const int q = tid / 11, j = tid % 11;
            const float* bs = (q == 2 || q == 3) ? sPT[2] : (q == 4 || q == 5) ? sPT[1] : sPT[0];
            const float4* vq = (const float4*)(v + q * 100);
            const float4* bj = (const float4*)(bs + j * 100);
            float s0 = 0.f, s1 = 0.f;
#pragma unroll
            for (int i = 0; i < 25; i++) {
                float4 a = vq[i], bb = bj[i];
                s0 = fmaf(a.x, bb.x, s0);
                s1 = fmaf(a.y, bb.y, s1);
                s0 = fmaf(a.z, bb.z, s0);
                s1 = fmaf(a.w, bb.w, s1);
            }
            red[tid] = s0 + s1;
        }
        __syncthreads();
        if (tid < 11) {
            const int j = tid;
            float Dx = 100.f * (red[j] + red[22 + j] + red[44 + j]);
            float Dy = 100.f * (red[11 + j] + red[33 + j] + red[55 + j] + red[66 + j]);
            float lxn = lxs[j] - Dx, lyn = lys[j] - Dy;
            lxs[j] = lxn; lys[j] = lyn;
            float mx = 0.f, my = 0.f;
#pragma unroll
            for (int i = 0; i < 11; i++) {
                mx = fmaf(cx[i], sMx[i * 11 + j], mx);
                my = fmaf(cy[i], sMy[i * 11 + j], my);
            }
            linx[j] = -lxn + Dx - cxb[j] - mx;
            liny[j] = -lyn + Dy - cyb[j] - my;
        }
        __syncthreads();
        if (tid < 22) {
            const int i = tid % 11;
            if (tid < 11) {
                float s = ex[i];
#pragma unroll
                for (int j = 0; j < 11; j++) s = fmaf(-sI2x[i * 14 + j], linx[j], s);
                cx[i] = s;
            } else {
                float s = ey[i];
#pragma unroll
                for (int j = 0; j < 11; j++) s = fmaf(-sI2y[i * 15 + j], liny[j], s);
                cy[i] = s;
            }
        }
    }
    __syncthreads();
    if (tid < 22) out[b * 22 + tid] = (tid < 11) ? cx[tid] : cy[tid - 11];
}

// ---------------- launch ----------------
extern "C" void kernel_launch(void* const* d_in, const int* in_sizes, int n_in,
                              void* d_out, int out_size)
{
    const float* inp  = (const float*)d_in[0];
    const float* ise  = (const float*)d_in[1];
    const float* traj = (const float*)d_in[2];
    const float* yub  = (const float*)d_in[3];
    const float* ylb  = (const float*)d_in[4];
    const float* eps  = (const float*)d_in[5];
    const float* ew1  = (const float*)d_in[6];
    const float* eb1  = (const float*)d_in[7];
    const float* ew2  = (const float*)d_in[8];
    const float* eb2  = (const float*)d_in[9];
    const float* wmu  = (const float*)d_in[10];
    const float* bmu  = (const float*)d_in[11];
    const float* wlv  = (const float*)d_in[12];
    const float* blv  = (const float*)d_in[13];
    const float* dw1  = (const float*)d_in[14];
    const float* db1  = (const float*)d_in[15];
    const float* dw2  = (const float*)d_in[16];
    const float* db2  = (const float*)d_in[17];
    const float* dw3  = (const float*)d_in[18];
    const float* db3  = (const float*)d_in[19];
    const float* P    = (const float*)d_in[20];
    const float* Pd   = (const float*)d_in[21];
    const float* Pdd  = (const float*)d_in[22];
    const float* imean = (const float*)d_in[23];
    const float* istd  = (const float*)d_in[24];
    float* out = (float*)d_out;

    bf16 *pX1h, *pX1l, *pH1h, *pH1l, *pH2h, *pH2l, *pX2h, *pX2l;
    bf16 *pT1h, *pT1l, *pT2h, *pT2l, *pT3h, *pT3l, *pT4h, *pT4l;
    cudaGetSymbolAddress((void**)&pX1h, g_X1h); cudaGetSymbolAddress((void**)&pX1l, g_X1l);
    cudaGetSymbolAddress((void**)&pH1h, g_H1h); cudaGetSymbolAddress((void**)&pH1l, g_H1l);
    cudaGetSymbolAddress((void**)&pH2h, g_H2h); cudaGetSymbolAddress((void**)&pH2l, g_H2l);
    cudaGetSymbolAddress((void**)&pX2h, g_X2h); cudaGetSymbolAddress((void**)&pX2l, g_X2l);
    cudaGetSymbolAddress((void**)&pT1h, g_T1h); cudaGetSymbolAddress((void**)&pT1l, g_T1l);
    cudaGetSymbolAddress((void**)&pT2h, g_T2h); cudaGetSymbolAddress((void**)&pT2l, g_T2l);
    cudaGetSymbolAddress((void**)&pT3h, g_T3h); cudaGetSymbolAddress((void**)&pT3l, g_T3l);
    cudaGetSymbolAddress((void**)&pT4h, g_T4h); cudaGetSymbolAddress((void**)&pT4l, g_T4l);

    setup_kernel<<<4, 128>>>(P, Pd, Pdd);

    dim3 tb(32, 8);
    convert_wt<<<dim3(32, 8),  tb>>>(ew1, pT1h, pT1l, 255,  1024, 256);
    convert_wt<<<dim3(32, 32), tb>>>(ew2, pT2h, pT2l, 1024, 1024, 1024);
    convert_wt<<<dim3(32, 2),  tb>>>(dw1, pT3h, pT3l, 57,   1024, 64);
    convert_wt<<<dim3(32, 32), tb>>>(dw2, pT4h, pT4l, 1024, 1024, 1024);

    build_x1<<<(NBATCH * 256) / 256, 256>>>(inp, traj, imean, istd);

    dim3 gg(16, 16);
    gemm_mma<<<gg, 256>>>(pX1h, pX1l, pT1h, pT1l, eb1, pH1h, pH1l, 256);
    gemm_mma<<<gg, 256>>>(pH1h, pH1l, pT2h, pT2l, eb2, pH2h, pH2l, 1024);
    zdec_kernel<<<NBATCH, 128>>>(wmu, bmu, wlv, blv, eps, inp, imean, istd);
    gemm_mma<<<gg, 256>>>(pX2h, pX2l, pT3h, pT3l, db1, pH1h, pH1l, 64);
    gemm_mma<<<gg, 256>>>(pH1h, pH1l, pT4h, pT4l, db2, pH2h, pH2l, 1024);
    nn8_kernel<<<NBATCH, 256>>>(dw3, db3);
    solver_kernel<<<NBATCH, 128>>>(P, Pd, Pdd, ise, yub, ylb, inp, out);
}